// round 2
// baseline (speedup 1.0000x reference)
#include <cuda_runtime.h>
#include <math.h>

#define Bsz   512
#define Tsz   256
#define Fsz   128
#define Hsz   512
#define FFsz  1024
#define OUTsz 64
#define H3    (3 * Hsz)
#define BT    (Bsz * Tsz)
#define PADV  (-999.0f)

// ---------------- scratch (static device globals; no allocations) ----------------
__device__ float g_GI[(size_t)BT * H3];     // 805 MB: x @ W_ih^T + b_ih
__device__ float g_ffin[(size_t)BT * Hsz];  // 256 MB: masked rnn_out (0 on pad)
__device__ float g_hid[(size_t)BT * FFsz];  // 512 MB: relu(ffin @ W1 + b1)
__device__ float g_h[2][Bsz * Hsz];         // double-buffered hidden state

// ---------------- packed f32x2 helpers (Blackwell FFMA2 path) ----------------
__device__ __forceinline__ unsigned long long pack2(float x, float y) {
    unsigned long long r;
    asm("mov.b64 %0,{%1,%2};" : "=l"(r) : "f"(x), "f"(y));
    return r;
}
__device__ __forceinline__ void fma2(unsigned long long& d, unsigned long long a,
                                     unsigned long long b) {
    asm("fma.rn.f32x2 %0,%1,%2,%0;" : "+l"(d) : "l"(a), "l"(b));
}
__device__ __forceinline__ void unpack2(unsigned long long v, float& x, float& y) {
    asm("mov.b64 {%0,%1},%2;" : "=f"(x), "=f"(y) : "l"(v));
}

// ---------------- init ----------------
__global__ void zero_h_kernel() {
    int i = blockIdx.x * blockDim.x + threadIdx.x;
    if (i < Bsz * Hsz) g_h[0][i] = 0.0f;
}

// ---------------- generic 128x128 tiled SGEMM: C = A @ B(^T) + bias, opt relu ----
// A: [M, KDIM] row-major. If BTRANS: Bm is [NDIM, KDIM] (use Bm^T). Else Bm is
// [KDIM, NDIM]. SKIP: tile rows all belong to one batch (128 | Tsz); if the
// whole tile is past seq_len, skip (consumer masks / never reads it).
template <int KDIM, int NDIM, bool BTRANS, bool RELU, bool SKIP>
__global__ __launch_bounds__(256) void sgemm128(const float* __restrict__ A,
                                                const float* __restrict__ Bm,
                                                const float* __restrict__ bias,
                                                float* __restrict__ C,
                                                const int* __restrict__ seq) {
    const int m0 = blockIdx.x * 128;
    const int n0 = blockIdx.y * 128;
    if (SKIP) {
        int b  = m0 / Tsz;
        int t0 = m0 % Tsz;
        if (t0 >= seq[b]) return;
    }
    __shared__ float As[16][128];
    __shared__ float Bs[16][128];
    const int tid  = threadIdx.x;
    const int tx   = tid % 16, ty = tid / 16;
    const int row0 = ty * 8, col0 = tx * 8;

    unsigned long long acc[8][4];
#pragma unroll
    for (int i = 0; i < 8; i++)
#pragma unroll
        for (int j = 0; j < 4; j++) acc[i][j] = 0ULL;

    for (int k0 = 0; k0 < KDIM; k0 += 16) {
        // A tile: 128 rows x 16 k, transposed into As[k][m]
#pragma unroll
        for (int l = 0; l < 2; l++) {
            int idx = tid + l * 256;
            int r = idx >> 2, c4 = (idx & 3) * 4;
            float4 v = *(const float4*)&A[(size_t)(m0 + r) * KDIM + k0 + c4];
            As[c4 + 0][r] = v.x; As[c4 + 1][r] = v.y;
            As[c4 + 2][r] = v.z; As[c4 + 3][r] = v.w;
        }
        if (BTRANS) {
#pragma unroll
            for (int l = 0; l < 2; l++) {
                int idx = tid + l * 256;
                int n = idx >> 2, c4 = (idx & 3) * 4;
                float4 v = *(const float4*)&Bm[(size_t)(n0 + n) * KDIM + k0 + c4];
                Bs[c4 + 0][n] = v.x; Bs[c4 + 1][n] = v.y;
                Bs[c4 + 2][n] = v.z; Bs[c4 + 3][n] = v.w;
            }
        } else {
#pragma unroll
            for (int l = 0; l < 2; l++) {
                int idx = tid + l * 256;
                int k = idx >> 5, c4 = (idx & 31) * 4;
                float4 v = *(const float4*)&Bm[(size_t)(k0 + k) * NDIM + n0 + c4];
                *(float4*)&Bs[k][c4] = v;
            }
        }
        __syncthreads();
#pragma unroll
        for (int k = 0; k < 16; k++) {
            float4 a0 = *(const float4*)&As[k][row0];
            float4 a1 = *(const float4*)&As[k][row0 + 4];
            unsigned long long bb[4];
#pragma unroll
            for (int j = 0; j < 4; j++)
                bb[j] = *(const unsigned long long*)&Bs[k][col0 + j * 2];
            float av[8] = {a0.x, a0.y, a0.z, a0.w, a1.x, a1.y, a1.z, a1.w};
#pragma unroll
            for (int i = 0; i < 8; i++) {
                unsigned long long ad = pack2(av[i], av[i]);
#pragma unroll
                for (int j = 0; j < 4; j++) fma2(acc[i][j], ad, bb[j]);
            }
        }
        __syncthreads();
    }
#pragma unroll
    for (int i = 0; i < 8; i++) {
        float out[8];
#pragma unroll
        for (int j = 0; j < 4; j++) unpack2(acc[i][j], out[j * 2], out[j * 2 + 1]);
#pragma unroll
        for (int j = 0; j < 8; j++) {
            float v = out[j] + bias[n0 + col0 + j];
            if (RELU) v = fmaxf(v, 0.0f);
            out[j] = v;
        }
        float4* cp = (float4*)&C[(size_t)(m0 + row0 + i) * NDIM + n0 + col0];
        cp[0] = make_float4(out[0], out[1], out[2], out[3]);
        cp[1] = make_float4(out[4], out[5], out[6], out[7]);
    }
}

// ---------------- GRU step: gh = h @ W_hh^T (+b_hh), gates, h update ----------
// Block tile: 64 batch rows x 32 hidden units x 3 gates. Grid (8, 16).
// Double-buffered h to avoid read/write races across blocks within a step.
__global__ __launch_bounds__(256) void gru_step_kernel(int t, int pp,
                                                       const float* __restrict__ W_hh,
                                                       const float* __restrict__ b_hh,
                                                       const int* __restrict__ seq) {
    __shared__ float As[32][64];       // h tile, transposed [k][m]
    __shared__ float Bs[3][32][32];    // W_hh tiles per gate, [k][n]
    const float* hin  = g_h[pp];
    float*       hout = g_h[pp ^ 1];
    const int m0 = blockIdx.x * 64;    // batch offset
    const int n0 = blockIdx.y * 32;    // hidden offset
    const int tid = threadIdx.x;
    const int tx = tid % 16, ty = tid / 16;

    unsigned long long aR[4], aZ[4], aN[4];
#pragma unroll
    for (int i = 0; i < 4; i++) { aR[i] = 0ULL; aZ[i] = 0ULL; aN[i] = 0ULL; }

    for (int k0 = 0; k0 < Hsz; k0 += 32) {
#pragma unroll
        for (int l = 0; l < 2; l++) {
            int idx = tid + l * 256;
            int r = idx >> 3, c4 = (idx & 7) * 4;
            float4 v = *(const float4*)&hin[(size_t)(m0 + r) * Hsz + k0 + c4];
            As[c4 + 0][r] = v.x; As[c4 + 1][r] = v.y;
            As[c4 + 2][r] = v.z; As[c4 + 3][r] = v.w;
        }
        {
            int n = tid >> 3, c4 = (tid & 7) * 4;
#pragma unroll
            for (int g = 0; g < 3; g++) {
                float4 v = *(const float4*)&W_hh[(size_t)(g * Hsz + n0 + n) * Hsz + k0 + c4];
                Bs[g][c4 + 0][n] = v.x; Bs[g][c4 + 1][n] = v.y;
                Bs[g][c4 + 2][n] = v.z; Bs[g][c4 + 3][n] = v.w;
            }
        }
        __syncthreads();
#pragma unroll
        for (int k = 0; k < 32; k++) {
            float4 a = *(const float4*)&As[k][ty * 4];
            unsigned long long br = *(const unsigned long long*)&Bs[0][k][tx * 2];
            unsigned long long bz = *(const unsigned long long*)&Bs[1][k][tx * 2];
            unsigned long long bn = *(const unsigned long long*)&Bs[2][k][tx * 2];
            float av[4] = {a.x, a.y, a.z, a.w};
#pragma unroll
            for (int i = 0; i < 4; i++) {
                unsigned long long ad = pack2(av[i], av[i]);
                fma2(aR[i], ad, br);
                fma2(aZ[i], ad, bz);
                fma2(aN[i], ad, bn);
            }
        }
        __syncthreads();
    }

#pragma unroll
    for (int i = 0; i < 4; i++) {
        int m = m0 + ty * 4 + i;
        int valid = (t < seq[m]) ? 1 : 0;
        size_t bt = (size_t)m * Tsz + t;
        float gr[2], gz[2], gn[2];
        unpack2(aR[i], gr[0], gr[1]);
        unpack2(aZ[i], gz[0], gz[1]);
        unpack2(aN[i], gn[0], gn[1]);
#pragma unroll
        for (int j = 0; j < 2; j++) {
            int n = n0 + tx * 2 + j;
            float ghr = gr[j] + b_hh[n];
            float ghz = gz[j] + b_hh[Hsz + n];
            float ghn = gn[j] + b_hh[2 * Hsz + n];
            size_t gib = bt * (size_t)H3 + n;
            float gir = g_GI[gib];
            float giz = g_GI[gib + Hsz];
            float gin = g_GI[gib + 2 * Hsz];
            float r  = 1.0f / (1.0f + __expf(-(gir + ghr)));
            float z  = 1.0f / (1.0f + __expf(-(giz + ghz)));
            float nn = tanhf(gin + r * ghn);
            float hp = hin[(size_t)m * Hsz + n];
            float hnew = (1.0f - z) * nn + z * hp;
            hout[(size_t)m * Hsz + n] = valid ? hnew : hp;
            g_ffin[bt * Hsz + n]      = valid ? hnew : 0.0f;
        }
    }
}

// ---------------- output GEMM: Y = hid @ W2 + b2, PAD-masked --------------------
// Block tile: 128 bt-rows x 64 (=OUT) cols. Grid (1024).
__global__ __launch_bounds__(256) void out_gemm_kernel(const float* __restrict__ W2,
                                                       const float* __restrict__ b2,
                                                       const int* __restrict__ seq,
                                                       float* __restrict__ Y) {
    const int m0 = blockIdx.x * 128;
    const int b  = m0 / Tsz;
    const int t0 = m0 % Tsz;
    const int tid = threadIdx.x;
    const int slen = seq[b];
    if (t0 >= slen) {
        float4 pv = make_float4(PADV, PADV, PADV, PADV);
#pragma unroll
        for (int l = 0; l < 8; l++) {
            int idx = tid + l * 256;  // float4 index in 128x64 tile
            *(float4*)&Y[(size_t)(m0 + (idx >> 4)) * OUTsz + (idx & 15) * 4] = pv;
        }
        return;
    }
    __shared__ float As[32][128];
    __shared__ float Bs[32][64];
    const int tx = tid % 16, ty = tid / 16;
    const int row0 = ty * 8, col0 = tx * 4;
    unsigned long long acc[8][2];
#pragma unroll
    for (int i = 0; i < 8; i++) { acc[i][0] = 0ULL; acc[i][1] = 0ULL; }

    for (int k0 = 0; k0 < FFsz; k0 += 32) {
#pragma unroll
        for (int l = 0; l < 4; l++) {
            int idx = tid + l * 256;
            int r = idx >> 3, c4 = (idx & 7) * 4;
            float4 v = *(const float4*)&g_hid[(size_t)(m0 + r) * FFsz + k0 + c4];
            As[c4 + 0][r] = v.x; As[c4 + 1][r] = v.y;
            As[c4 + 2][r] = v.z; As[c4 + 3][r] = v.w;
        }
#pragma unroll
        for (int l = 0; l < 2; l++) {
            int idx = tid + l * 256;
            int k = idx >> 4, c4 = (idx & 15) * 4;
            *(float4*)&Bs[k][c4] = *(const float4*)&W2[(size_t)(k0 + k) * OUTsz + c4];
        }
        __syncthreads();
#pragma unroll
        for (int k = 0; k < 32; k++) {
            float4 a0 = *(const float4*)&As[k][row0];
            float4 a1 = *(const float4*)&As[k][row0 + 4];
            unsigned long long b0 = *(const unsigned long long*)&Bs[k][col0];
            unsigned long long b1 = *(const unsigned long long*)&Bs[k][col0 + 2];
            float av[8] = {a0.x, a0.y, a0.z, a0.w, a1.x, a1.y, a1.z, a1.w};
#pragma unroll
            for (int i = 0; i < 8; i++) {
                unsigned long long ad = pack2(av[i], av[i]);
                fma2(acc[i][0], ad, b0);
                fma2(acc[i][1], ad, b1);
            }
        }
        __syncthreads();
    }
#pragma unroll
    for (int i = 0; i < 8; i++) {
        int m = m0 + row0 + i;
        int t = t0 + row0 + i;
        float o[4];
        unpack2(acc[i][0], o[0], o[1]);
        unpack2(acc[i][1], o[2], o[3]);
        float4 v;
        if (t < slen) {
            v = make_float4(o[0] + b2[col0 + 0], o[1] + b2[col0 + 1],
                            o[2] + b2[col0 + 2], o[3] + b2[col0 + 3]);
        } else {
            v = make_float4(PADV, PADV, PADV, PADV);
        }
        *(float4*)&Y[(size_t)m * OUTsz + col0] = v;
    }
}

// ---------------- launch ----------------
extern "C" void kernel_launch(void* const* d_in, const int* in_sizes, int n_in,
                              void* d_out, int out_size) {
    (void)in_sizes; (void)n_in; (void)out_size;
    const float* x    = (const float*)d_in[0];
    const int*   seq  = (const int*)d_in[1];
    const float* W_ih = (const float*)d_in[2];
    const float* W_hh = (const float*)d_in[3];
    const float* b_ih = (const float*)d_in[4];
    const float* b_hh = (const float*)d_in[5];
    const float* W1   = (const float*)d_in[6];
    const float* b1   = (const float*)d_in[7];
    const float* W2   = (const float*)d_in[8];
    const float* b2   = (const float*)d_in[9];
    float* Y = (float*)d_out;

    float *pGI = nullptr, *pFF = nullptr, *pHID = nullptr;
    cudaGetSymbolAddress((void**)&pGI, g_GI);
    cudaGetSymbolAddress((void**)&pFF, g_ffin);
    cudaGetSymbolAddress((void**)&pHID, g_hid);

    // 1) h0 = 0
    zero_h_kernel<<<(Bsz * Hsz + 255) / 256, 256>>>();

    // 2) GI = x @ W_ih^T + b_ih   (full-pad tiles skipped)
    sgemm128<Fsz, H3, true, false, true>
        <<<dim3(BT / 128, H3 / 128), 256>>>(x, W_ih, b_ih, pGI, seq);

    // 3) sequential GRU over T steps (double-buffered h)
    for (int t = 0; t < Tsz; t++) {
        gru_step_kernel<<<dim3(Bsz / 64, Hsz / 32), 256>>>(t, t & 1, W_hh, b_hh, seq);
    }

    // 4) HID = relu(ffin @ W1 + b1)   (full-pad tiles skipped)
    sgemm128<Hsz, FFsz, false, true, true>
        <<<dim3(BT / 128, FFsz / 128), 256>>>(pFF, W1, b1, pHID, seq);

    // 5) Y = hid @ W2 + b2, PAD-masked
    out_gemm_kernel<<<dim3(BT / 128), 256>>>(W2, b2, seq, Y);
}

// round 3
// speedup vs baseline: 1.3455x; 1.3455x over previous
#include <cuda_runtime.h>
#include <math.h>

#define Bsz   512
#define Tsz   256
#define Fsz   128
#define Hsz   512
#define FFsz  1024
#define OUTsz 64
#define H3    (3 * Hsz)
#define BT    (Bsz * Tsz)
#define PADV  (-999.0f)
#define KT    32

__device__ float g_GI[(size_t)BT * H3];
__device__ float g_ffin[(size_t)BT * Hsz];
__device__ float g_hid[(size_t)BT * FFsz];
__device__ float g_h[2][Bsz * Hsz];
__device__ unsigned int g_bar;

__device__ __forceinline__ unsigned long long pack2(float x, float y) {
    unsigned long long r;
    asm("mov.b64 %0,{%1,%2};" : "=l"(r) : "f"(x), "f"(y));
    return r;
}
__device__ __forceinline__ void fma2(unsigned long long& d, unsigned long long a,
                                     unsigned long long b) {
    asm("fma.rn.f32x2 %0,%1,%2,%0;" : "+l"(d) : "l"(a), "l"(b));
}
__device__ __forceinline__ void unpack2(unsigned long long v, float& x, float& y) {
    asm("mov.b64 {%0,%1},%2;" : "=f"(x), "=f"(y) : "l"(v));
}

__global__ void init_kernel() {
    int i = blockIdx.x * blockDim.x + threadIdx.x;
    if (i < Bsz * Hsz) g_h[0][i] = 0.0f;
    if (i == 0) g_bar = 0u;
}

// ---------- generic 128x128 SGEMM (unchanged; ~near packed-FFMA2 peak) ----------
template <int KDIM, int NDIM, bool BTRANS, bool RELU, bool SKIP>
__global__ __launch_bounds__(256) void sgemm128(const float* __restrict__ A,
                                                const float* __restrict__ Bm,
                                                const float* __restrict__ bias,
                                                float* __restrict__ C,
                                                const int* __restrict__ seq) {
    const int m0 = blockIdx.x * 128;
    const int n0 = blockIdx.y * 128;
    if (SKIP) {
        int b = m0 / Tsz, t0 = m0 % Tsz;
        if (t0 >= seq[b]) return;
    }
    __shared__ float As[16][128];
    __shared__ float Bs[16][128];
    const int tid = threadIdx.x;
    const int tx = tid % 16, ty = tid / 16;
    const int row0 = ty * 8, col0 = tx * 8;
    unsigned long long acc[8][4];
#pragma unroll
    for (int i = 0; i < 8; i++)
#pragma unroll
        for (int j = 0; j < 4; j++) acc[i][j] = 0ULL;

    for (int k0 = 0; k0 < KDIM; k0 += 16) {
#pragma unroll
        for (int l = 0; l < 2; l++) {
            int idx = tid + l * 256;
            int r = idx >> 2, c4 = (idx & 3) * 4;
            float4 v = *(const float4*)&A[(size_t)(m0 + r) * KDIM + k0 + c4];
            As[c4 + 0][r] = v.x; As[c4 + 1][r] = v.y;
            As[c4 + 2][r] = v.z; As[c4 + 3][r] = v.w;
        }
        if (BTRANS) {
#pragma unroll
            for (int l = 0; l < 2; l++) {
                int idx = tid + l * 256;
                int n = idx >> 2, c4 = (idx & 3) * 4;
                float4 v = *(const float4*)&Bm[(size_t)(n0 + n) * KDIM + k0 + c4];
                Bs[c4 + 0][n] = v.x; Bs[c4 + 1][n] = v.y;
                Bs[c4 + 2][n] = v.z; Bs[c4 + 3][n] = v.w;
            }
        } else {
#pragma unroll
            for (int l = 0; l < 2; l++) {
                int idx = tid + l * 256;
                int k = idx >> 5, c4 = (idx & 31) * 4;
                *(float4*)&Bs[k][c4] =
                    *(const float4*)&Bm[(size_t)(k0 + k) * NDIM + n0 + c4];
            }
        }
        __syncthreads();
#pragma unroll
        for (int k = 0; k < 16; k++) {
            float4 a0 = *(const float4*)&As[k][row0];
            float4 a1 = *(const float4*)&As[k][row0 + 4];
            unsigned long long bb[4];
#pragma unroll
            for (int j = 0; j < 4; j++)
                bb[j] = *(const unsigned long long*)&Bs[k][col0 + j * 2];
            float av[8] = {a0.x, a0.y, a0.z, a0.w, a1.x, a1.y, a1.z, a1.w};
#pragma unroll
            for (int i = 0; i < 8; i++) {
                unsigned long long ad = pack2(av[i], av[i]);
#pragma unroll
                for (int j = 0; j < 4; j++) fma2(acc[i][j], ad, bb[j]);
            }
        }
        __syncthreads();
    }
#pragma unroll
    for (int i = 0; i < 8; i++) {
        float out[8];
#pragma unroll
        for (int j = 0; j < 4; j++) unpack2(acc[i][j], out[j * 2], out[j * 2 + 1]);
#pragma unroll
        for (int j = 0; j < 8; j++) {
            float v = out[j] + bias[n0 + col0 + j];
            if (RELU) v = fmaxf(v, 0.0f);
            out[j] = v;
        }
        float4* cp = (float4*)&C[(size_t)(m0 + row0 + i) * NDIM + n0 + col0];
        cp[0] = make_float4(out[0], out[1], out[2], out[3]);
        cp[1] = make_float4(out[4], out[5], out[6], out[7]);
    }
}

// ---------- persistent GRU: all 256 steps in ONE kernel --------------------------
// Grid = 128 blocks (all resident). Block owns a (64 batch x 32 hid x 3 gate) tile.
// Software grid barrier between steps; ping-pong h read via __ldcg (L2-coherent).
__global__ __launch_bounds__(256, 1) void gru_persist(
    const float* __restrict__ GI, const float* __restrict__ W_hh,
    const float* __restrict__ b_hh, const int* __restrict__ seq,
    float* __restrict__ ffin) {
    __shared__ float As[2][KT][68];   // [buf][k][m]
    __shared__ float Bs[2][KT][97];   // [buf][k][g*32+n]

    const int tid = threadIdx.x;
    const int tx  = tid & 31;          // n lane
    const int ty  = tid >> 5;          // m octet (warp id)
    const int m0  = (blockIdx.x >> 4) * 64;
    const int n0  = (blockIdx.x & 15) * 32;
    const int n   = n0 + tx;

    const float bhr = b_hh[n];
    const float bhz = b_hh[Hsz + n];
    const float bhn = b_hh[2 * Hsz + n];
    int slen[8];
#pragma unroll
    for (int i = 0; i < 8; i++) slen[i] = seq[m0 + ty * 8 + i];

    const int fr  = tid >> 3;          // 0..31
    const int fc4 = (tid & 7) * 4;     // 0,4,...,28
    const float* wp0 = &W_hh[(size_t)(0 * Hsz + n0 + fr) * Hsz + fc4];
    const float* wp1 = &W_hh[(size_t)(1 * Hsz + n0 + fr) * Hsz + fc4];
    const float* wp2 = &W_hh[(size_t)(2 * Hsz + n0 + fr) * Hsz + fc4];

    for (int t = 0; t < Tsz; ++t) {
        const int pp = t & 1;
        const float* __restrict__ hin  = g_h[pp];
        float* __restrict__       hout = g_h[pp ^ 1];

        unsigned long long aR[4], aZ[4], aN[4];
#pragma unroll
        for (int p = 0; p < 4; p++) { aR[p] = 0ULL; aZ[p] = 0ULL; aN[p] = 0ULL; }

        float4 pa0, pa1, pb0, pb1, pb2;
        pa0 = __ldcg((const float4*)&hin[(size_t)(m0 + fr) * Hsz + fc4]);
        pa1 = __ldcg((const float4*)&hin[(size_t)(m0 + fr + 32) * Hsz + fc4]);
        pb0 = *(const float4*)(wp0);
        pb1 = *(const float4*)(wp1);
        pb2 = *(const float4*)(wp2);

        auto sts = [&](int b) {
            As[b][fc4 + 0][fr] = pa0.x; As[b][fc4 + 1][fr] = pa0.y;
            As[b][fc4 + 2][fr] = pa0.z; As[b][fc4 + 3][fr] = pa0.w;
            As[b][fc4 + 0][fr + 32] = pa1.x; As[b][fc4 + 1][fr + 32] = pa1.y;
            As[b][fc4 + 2][fr + 32] = pa1.z; As[b][fc4 + 3][fr + 32] = pa1.w;
            Bs[b][fc4 + 0][fr] = pb0.x; Bs[b][fc4 + 1][fr] = pb0.y;
            Bs[b][fc4 + 2][fr] = pb0.z; Bs[b][fc4 + 3][fr] = pb0.w;
            Bs[b][fc4 + 0][32 + fr] = pb1.x; Bs[b][fc4 + 1][32 + fr] = pb1.y;
            Bs[b][fc4 + 2][32 + fr] = pb1.z; Bs[b][fc4 + 3][32 + fr] = pb1.w;
            Bs[b][fc4 + 0][64 + fr] = pb2.x; Bs[b][fc4 + 1][64 + fr] = pb2.y;
            Bs[b][fc4 + 2][64 + fr] = pb2.z; Bs[b][fc4 + 3][64 + fr] = pb2.w;
        };
        sts(0);
        __syncthreads();

#pragma unroll 1
        for (int ch = 0; ch < Hsz / KT; ++ch) {
            const int cb = ch & 1;
            if (ch < Hsz / KT - 1) {
                const int k0 = (ch + 1) * KT;
                pa0 = __ldcg((const float4*)&hin[(size_t)(m0 + fr) * Hsz + k0 + fc4]);
                pa1 = __ldcg((const float4*)&hin[(size_t)(m0 + fr + 32) * Hsz + k0 + fc4]);
                pb0 = *(const float4*)(wp0 + k0);
                pb1 = *(const float4*)(wp1 + k0);
                pb2 = *(const float4*)(wp2 + k0);
            }
#pragma unroll
            for (int k = 0; k < KT; ++k) {
                ulonglong2 a01 = *(const ulonglong2*)&As[cb][k][ty * 8];
                ulonglong2 a23 = *(const ulonglong2*)&As[cb][k][ty * 8 + 4];
                float br = Bs[cb][k][tx];
                float bz = Bs[cb][k][32 + tx];
                float bv = Bs[cb][k][64 + tx];
                unsigned long long brr = pack2(br, br);
                unsigned long long bzz = pack2(bz, bz);
                unsigned long long bnn = pack2(bv, bv);
                fma2(aR[0], a01.x, brr); fma2(aR[1], a01.y, brr);
                fma2(aR[2], a23.x, brr); fma2(aR[3], a23.y, brr);
                fma2(aZ[0], a01.x, bzz); fma2(aZ[1], a01.y, bzz);
                fma2(aZ[2], a23.x, bzz); fma2(aZ[3], a23.y, bzz);
                fma2(aN[0], a01.x, bnn); fma2(aN[1], a01.y, bnn);
                fma2(aN[2], a23.x, bnn); fma2(aN[3], a23.y, bnn);
            }
            if (ch < Hsz / KT - 1) sts(cb ^ 1);
            __syncthreads();
        }

#pragma unroll
        for (int p = 0; p < 4; ++p) {
            float rr[2], zz[2], nv[2];
            unpack2(aR[p], rr[0], rr[1]);
            unpack2(aZ[p], zz[0], zz[1]);
            unpack2(aN[p], nv[0], nv[1]);
#pragma unroll
            for (int j = 0; j < 2; ++j) {
                const int mi = p * 2 + j;
                const int m  = m0 + ty * 8 + mi;
                const float hp = __ldcg(&hin[(size_t)m * Hsz + n]);
                if (t < slen[mi]) {
                    const size_t bt = (size_t)m * Tsz + t;
                    const float* gi = &GI[bt * (size_t)H3 + n];
                    const float gir = gi[0];
                    const float giz = gi[Hsz];
                    const float gin = gi[2 * Hsz];
                    const float r = __fdividef(1.0f, 1.0f + __expf(-(gir + rr[j] + bhr)));
                    const float z = __fdividef(1.0f, 1.0f + __expf(-(giz + zz[j] + bhz)));
                    const float nn = tanhf(gin + r * (nv[j] + bhn));
                    const float hnew = (1.0f - z) * nn + z * hp;
                    hout[(size_t)m * Hsz + n] = hnew;
                    ffin[bt * (size_t)Hsz + n] = hnew;
                } else {
                    hout[(size_t)m * Hsz + n] = hp;
                }
            }
        }

        if (t < Tsz - 1) {
            __syncthreads();
            if (tid == 0) {
                __threadfence();
                atomicAdd(&g_bar, 1u);
                const unsigned target = (unsigned)(t + 1) * (unsigned)gridDim.x;
                while (atomicAdd(&g_bar, 0u) < target) __nanosleep(64);
            }
            __syncthreads();
        }
    }
}

// ---------- output GEMM: Y = hid @ W2 + b2, PAD-masked ---------------------------
__global__ __launch_bounds__(256) void out_gemm_kernel(const float* __restrict__ W2,
                                                       const float* __restrict__ b2,
                                                       const int* __restrict__ seq,
                                                       float* __restrict__ Y) {
    const int m0 = blockIdx.x * 128;
    const int b  = m0 / Tsz;
    const int t0 = m0 % Tsz;
    const int tid = threadIdx.x;
    const int slen = seq[b];
    if (t0 >= slen) {
        float4 pv = make_float4(PADV, PADV, PADV, PADV);
#pragma unroll
        for (int l = 0; l < 8; l++) {
            int idx = tid + l * 256;
            *(float4*)&Y[(size_t)(m0 + (idx >> 4)) * OUTsz + (idx & 15) * 4] = pv;
        }
        return;
    }
    __shared__ float As[32][128];
    __shared__ float Bs[32][64];
    const int tx = tid % 16, ty = tid / 16;
    const int row0 = ty * 8, col0 = tx * 4;
    unsigned long long acc[8][2];
#pragma unroll
    for (int i = 0; i < 8; i++) { acc[i][0] = 0ULL; acc[i][1] = 0ULL; }

    for (int k0 = 0; k0 < FFsz; k0 += 32) {
#pragma unroll
        for (int l = 0; l < 4; l++) {
            int idx = tid + l * 256;
            int r = idx >> 3, c4 = (idx & 7) * 4;
            float4 v = *(const float4*)&g_hid[(size_t)(m0 + r) * FFsz + k0 + c4];
            As[c4 + 0][r] = v.x; As[c4 + 1][r] = v.y;
            As[c4 + 2][r] = v.z; As[c4 + 3][r] = v.w;
        }
#pragma unroll
        for (int l = 0; l < 2; l++) {
            int idx = tid + l * 256;
            int k = idx >> 4, c4 = (idx & 15) * 4;
            *(float4*)&Bs[k][c4] = *(const float4*)&W2[(size_t)(k0 + k) * OUTsz + c4];
        }
        __syncthreads();
#pragma unroll
        for (int k = 0; k < 32; k++) {
            float4 a0 = *(const float4*)&As[k][row0];
            float4 a1 = *(const float4*)&As[k][row0 + 4];
            unsigned long long b0 = *(const unsigned long long*)&Bs[k][col0];
            unsigned long long b1 = *(const unsigned long long*)&Bs[k][col0 + 2];
            float av[8] = {a0.x, a0.y, a0.z, a0.w, a1.x, a1.y, a1.z, a1.w};
#pragma unroll
            for (int i = 0; i < 8; i++) {
                unsigned long long ad = pack2(av[i], av[i]);
                fma2(acc[i][0], ad, b0);
                fma2(acc[i][1], ad, b1);
            }
        }
        __syncthreads();
    }
#pragma unroll
    for (int i = 0; i < 8; i++) {
        int m = m0 + row0 + i;
        int t = t0 + row0 + i;
        float o[4];
        unpack2(acc[i][0], o[0], o[1]);
        unpack2(acc[i][1], o[2], o[3]);
        float4 v;
        if (t < slen) {
            v = make_float4(o[0] + b2[col0 + 0], o[1] + b2[col0 + 1],
                            o[2] + b2[col0 + 2], o[3] + b2[col0 + 3]);
        } else {
            v = make_float4(PADV, PADV, PADV, PADV);
        }
        *(float4*)&Y[(size_t)m * OUTsz + col0] = v;
    }
}

// ---------- launch ----------
extern "C" void kernel_launch(void* const* d_in, const int* in_sizes, int n_in,
                              void* d_out, int out_size) {
    (void)in_sizes; (void)n_in; (void)out_size;
    const float* x    = (const float*)d_in[0];
    const int*   seq  = (const int*)d_in[1];
    const float* W_ih = (const float*)d_in[2];
    const float* W_hh = (const float*)d_in[3];
    const float* b_ih = (const float*)d_in[4];
    const float* b_hh = (const float*)d_in[5];
    const float* W1   = (const float*)d_in[6];
    const float* b1   = (const float*)d_in[7];
    const float* W2   = (const float*)d_in[8];
    const float* b2   = (const float*)d_in[9];
    float* Y = (float*)d_out;

    float *pGI = nullptr, *pFF = nullptr, *pHID = nullptr;
    cudaGetSymbolAddress((void**)&pGI, g_GI);
    cudaGetSymbolAddress((void**)&pFF, g_ffin);
    cudaGetSymbolAddress((void**)&pHID, g_hid);

    init_kernel<<<(Bsz * Hsz + 255) / 256, 256>>>();

    sgemm128<Fsz, H3, true, false, true>
        <<<dim3(BT / 128, H3 / 128), 256>>>(x, W_ih, b_ih, pGI, seq);

    gru_persist<<<128, 256>>>(pGI, W_hh, b_hh, seq, pFF);

    sgemm128<Hsz, FFsz, false, true, true>
        <<<dim3(BT / 128, FFsz / 128), 256>>>(pFF, W1, b1, pHID, seq);

    out_gemm_kernel<<<dim3(BT / 128), 256>>>(W2, b2, seq, Y);
}

// round 4
// speedup vs baseline: 1.5992x; 1.1885x over previous
#include <cuda_runtime.h>
#include <cuda_bf16.h>
#include <math.h>

#define Bsz   512
#define Tsz   256
#define Fsz   128
#define Hsz   512
#define FFsz  1024
#define OUTsz 64
#define H3    (3 * Hsz)
#define BT    (Bsz * Tsz)
#define PADV  (-999.0f)

// ---------------- scratch ----------------
__device__ float g_GI[(size_t)BT * H3];
__device__ float g_ffin[(size_t)BT * Hsz];
__device__ float g_hid[(size_t)BT * FFsz];
__device__ float g_h[2][Bsz * Hsz];
__device__ __nv_bfloat16 g_hbf_hi[2][Bsz * Hsz];
__device__ __nv_bfloat16 g_hbf_lo[2][Bsz * Hsz];
// W_hh pre-formatted into mma fragment layout:
// [block_n(16)][kt(32)][nw(2)][g(3)][lane(32)][8 words]
__device__ unsigned int g_wfrag[16 * 32 * 2 * 3 * 32 * 8];
__device__ unsigned int g_bar;

// ---------------- packed f32x2 helpers (sgemm path) ----------------
__device__ __forceinline__ unsigned long long pack2(float x, float y) {
    unsigned long long r;
    asm("mov.b64 %0,{%1,%2};" : "=l"(r) : "f"(x), "f"(y));
    return r;
}
__device__ __forceinline__ void fma2(unsigned long long& d, unsigned long long a,
                                     unsigned long long b) {
    asm("fma.rn.f32x2 %0,%1,%2,%0;" : "+l"(d) : "l"(a), "l"(b));
}
__device__ __forceinline__ void unpack2(unsigned long long v, float& x, float& y) {
    asm("mov.b64 {%0,%1},%2;" : "=f"(x), "=f"(y) : "l"(v));
}

__device__ __forceinline__ void mma_bf16(float* d, unsigned a0, unsigned a1,
                                         unsigned a2, unsigned a3,
                                         unsigned b0, unsigned b1) {
    asm volatile(
        "mma.sync.aligned.m16n8k16.row.col.f32.bf16.bf16.f32 "
        "{%0,%1,%2,%3},{%4,%5,%6,%7},{%8,%9},{%0,%1,%2,%3};"
        : "+f"(d[0]), "+f"(d[1]), "+f"(d[2]), "+f"(d[3])
        : "r"(a0), "r"(a1), "r"(a2), "r"(a3), "r"(b0), "r"(b1));
}

__device__ __forceinline__ unsigned bf2pack(float x, float y) {
    __nv_bfloat162 v = __floats2bfloat162_rn(x, y);
    return *(unsigned*)&v;
}

// ---------------- init ----------------
__global__ void init_kernel() {
    int i = blockIdx.x * blockDim.x + threadIdx.x;
    if (i < Bsz * Hsz) {
        g_h[0][i] = 0.0f;
        g_hbf_hi[0][i] = __float2bfloat16(0.0f);
        g_hbf_lo[0][i] = __float2bfloat16(0.0f);
    }
    if (i == 0) g_bar = 0u;
}

// ---------------- W_hh -> bf16 hi/lo fragment layout (runs once per call) -------
__global__ void wprep_kernel(const float* __restrict__ W_hh) {
    int idx = blockIdx.x * blockDim.x + threadIdx.x;   // 0..98303
    if (idx >= 16 * 32 * 2 * 3 * 32) return;
    int lane = idx & 31;
    int r = idx >> 5;
    int g = r % 3;  r /= 3;
    int nw = r & 1; r >>= 1;
    int kt = r & 31;
    int bn = r >> 5;
    int grp = lane >> 2, thr = lane & 3;

    unsigned w[8];
#pragma unroll
    for (int j = 0; j < 2; j++) {
        int n_row = g * Hsz + bn * 32 + nw * 16 + j * 8 + grp;
        const float* src = &W_hh[(size_t)n_row * Hsz + kt * 16 + thr * 2];
        float x0 = src[0], x1 = src[1], x8 = src[8], x9 = src[9];
        unsigned b0h = bf2pack(x0, x1);
        unsigned b1h = bf2pack(x8, x9);
        __nv_bfloat162 h0 = *(__nv_bfloat162*)&b0h;
        __nv_bfloat162 h1 = *(__nv_bfloat162*)&b1h;
        unsigned b0l = bf2pack(x0 - __bfloat162float(__low2bfloat16(h0)),
                               x1 - __bfloat162float(__high2bfloat16(h0)));
        unsigned b1l = bf2pack(x8 - __bfloat162float(__low2bfloat16(h1)),
                               x9 - __bfloat162float(__high2bfloat16(h1)));
        w[0 + j * 2] = b0h; w[1 + j * 2] = b1h;
        w[4 + j * 2] = b0l; w[5 + j * 2] = b1l;
    }
    unsigned* dst = &g_wfrag[(size_t)((((bn * 32 + kt) * 2 + nw) * 3 + g) * 32 + lane) * 8];
#pragma unroll
    for (int i = 0; i < 8; i++) dst[i] = w[i];
}

// ---------------- generic 128x128 SGEMM (unchanged) ------------------------------
template <int KDIM, int NDIM, bool BTRANS, bool RELU, bool SKIP>
__global__ __launch_bounds__(256) void sgemm128(const float* __restrict__ A,
                                                const float* __restrict__ Bm,
                                                const float* __restrict__ bias,
                                                float* __restrict__ C,
                                                const int* __restrict__ seq) {
    const int m0 = blockIdx.x * 128;
    const int n0 = blockIdx.y * 128;
    if (SKIP) {
        int b = m0 / Tsz, t0 = m0 % Tsz;
        if (t0 >= seq[b]) return;
    }
    __shared__ float As[16][128];
    __shared__ float Bs[16][128];
    const int tid = threadIdx.x;
    const int tx = tid % 16, ty = tid / 16;
    const int row0 = ty * 8, col0 = tx * 8;
    unsigned long long acc[8][4];
#pragma unroll
    for (int i = 0; i < 8; i++)
#pragma unroll
        for (int j = 0; j < 4; j++) acc[i][j] = 0ULL;

    for (int k0 = 0; k0 < KDIM; k0 += 16) {
#pragma unroll
        for (int l = 0; l < 2; l++) {
            int idx = tid + l * 256;
            int r = idx >> 2, c4 = (idx & 3) * 4;
            float4 v = *(const float4*)&A[(size_t)(m0 + r) * KDIM + k0 + c4];
            As[c4 + 0][r] = v.x; As[c4 + 1][r] = v.y;
            As[c4 + 2][r] = v.z; As[c4 + 3][r] = v.w;
        }
        if (BTRANS) {
#pragma unroll
            for (int l = 0; l < 2; l++) {
                int idx = tid + l * 256;
                int n = idx >> 2, c4 = (idx & 3) * 4;
                float4 v = *(const float4*)&Bm[(size_t)(n0 + n) * KDIM + k0 + c4];
                Bs[c4 + 0][n] = v.x; Bs[c4 + 1][n] = v.y;
                Bs[c4 + 2][n] = v.z; Bs[c4 + 3][n] = v.w;
            }
        } else {
#pragma unroll
            for (int l = 0; l < 2; l++) {
                int idx = tid + l * 256;
                int k = idx >> 5, c4 = (idx & 31) * 4;
                *(float4*)&Bs[k][c4] =
                    *(const float4*)&Bm[(size_t)(k0 + k) * NDIM + n0 + c4];
            }
        }
        __syncthreads();
#pragma unroll
        for (int k = 0; k < 16; k++) {
            float4 a0 = *(const float4*)&As[k][row0];
            float4 a1 = *(const float4*)&As[k][row0 + 4];
            unsigned long long bb[4];
#pragma unroll
            for (int j = 0; j < 4; j++)
                bb[j] = *(const unsigned long long*)&Bs[k][col0 + j * 2];
            float av[8] = {a0.x, a0.y, a0.z, a0.w, a1.x, a1.y, a1.z, a1.w};
#pragma unroll
            for (int i = 0; i < 8; i++) {
                unsigned long long ad = pack2(av[i], av[i]);
#pragma unroll
                for (int j = 0; j < 4; j++) fma2(acc[i][j], ad, bb[j]);
            }
        }
        __syncthreads();
    }
#pragma unroll
    for (int i = 0; i < 8; i++) {
        float out[8];
#pragma unroll
        for (int j = 0; j < 4; j++) unpack2(acc[i][j], out[j * 2], out[j * 2 + 1]);
#pragma unroll
        for (int j = 0; j < 8; j++) {
            float v = out[j] + bias[n0 + col0 + j];
            if (RELU) v = fmaxf(v, 0.0f);
            out[j] = v;
        }
        float4* cp = (float4*)&C[(size_t)(m0 + row0 + i) * NDIM + n0 + col0];
        cp[0] = make_float4(out[0], out[1], out[2], out[3]);
        cp[1] = make_float4(out[4], out[5], out[6], out[7]);
    }
}

// ---------------- persistent tensor-core GRU -------------------------------------
// Grid=128: block = (m0 = (bid>>4)*64 batch rows) x (block_n = bid&15 -> 32 hidden).
// Warp (8): mw = wid&3 (16 m rows), nw = wid>>2 (16 hidden cols = 2 n8-tiles x 3 gates).
// gh = h @ W_hh^T via mma.sync bf16, hi/lo split (3 mma per frag pair), fp32 accum.
#define AW_STRIDE 260                       // words per A row (512 bf16 + pad)
#define A_WORDS   (64 * AW_STRIDE)          // per hi / lo array
#define B_CHUNK_W 1536                      // words per kt chunk (2*3*32*8)

__global__ __launch_bounds__(256, 1) void gru_mma(
    const float* __restrict__ GI, const float* __restrict__ b_hh,
    const int* __restrict__ seq, float* __restrict__ ffin) {
    extern __shared__ unsigned smemw[];
    unsigned* Ahi = smemw;
    unsigned* Alo = smemw + A_WORDS;
    unsigned* Bw  = smemw + 2 * A_WORDS;    // [2][B_CHUNK_W]

    const int tid = threadIdx.x;
    const int lane = tid & 31;
    const int wid  = tid >> 5;
    const int mw = wid & 3, nw = wid >> 2;
    const int grp = lane >> 2, thr = lane & 3;
    const int m0 = (blockIdx.x >> 4) * 64;
    const int block_n = blockIdx.x & 15;
    const int hb = block_n * 32;

    const int m_a = m0 + mw * 16 + grp;
    const int m_b = m_a + 8;
    const int seq_a = seq[m_a];
    const int seq_b = seq[m_b];

    // hoist b_hh pairs: [j][gate]
    float2 bh[2][3];
#pragma unroll
    for (int j = 0; j < 2; j++) {
        const int hcol = hb + nw * 16 + j * 8 + thr * 2;
#pragma unroll
        for (int g = 0; g < 3; g++) bh[j][g] = *(const float2*)&b_hh[g * Hsz + hcol];
    }

    const size_t wbase_blk = (size_t)block_n * 32 * B_CHUNK_W;

    for (int t = 0; t < Tsz; ++t) {
        const int pp = t & 1;
        const float* __restrict__ hin = g_h[pp];
        float* __restrict__ hout = g_h[pp ^ 1];
        const __nv_bfloat16* __restrict__ hbh_in = g_hbf_hi[pp];
        const __nv_bfloat16* __restrict__ hbl_in = g_hbf_lo[pp];
        __nv_bfloat16* __restrict__ hbh_out = g_hbf_hi[pp ^ 1];
        __nv_bfloat16* __restrict__ hbl_out = g_hbf_lo[pp ^ 1];

        // ---- fill A (h slice, bf16 hi/lo) into smem: 64 rows x 64 granules each
#pragma unroll 4
        for (int it = 0; it < 16; it++) {
            int gi = tid + it * 256;
            int row = gi >> 6, c16 = gi & 63;
            uint4 v = __ldcg((const uint4*)&hbh_in[((size_t)(m0 + row) << 9) + c16 * 8]);
            *(uint4*)&Ahi[row * AW_STRIDE + c16 * 4] = v;
            uint4 w = __ldcg((const uint4*)&hbl_in[((size_t)(m0 + row) << 9) + c16 * 8]);
            *(uint4*)&Alo[row * AW_STRIDE + c16 * 4] = w;
        }
        // ---- preload B chunk 0
        {
            const uint4* src = (const uint4*)&g_wfrag[wbase_blk];
            ((uint4*)Bw)[tid] = src[tid];
            if (tid < 128) ((uint4*)Bw)[256 + tid] = src[256 + tid];
        }
        __syncthreads();

        float acc[2][3][4];
#pragma unroll
        for (int j = 0; j < 2; j++)
#pragma unroll
            for (int g = 0; g < 3; g++)
#pragma unroll
                for (int c = 0; c < 4; c++) acc[j][g][c] = 0.0f;

#pragma unroll 1
        for (int kt = 0; kt < 32; ++kt) {
            const int cb = kt & 1;
            uint4 p1, p2;
            const bool havep = (kt < 31);
            if (havep) {
                const uint4* src = (const uint4*)&g_wfrag[wbase_blk + (size_t)(kt + 1) * B_CHUNK_W];
                p1 = src[tid];
                if (tid < 128) p2 = src[256 + tid];
            }
            // A fragments
            const int abase = (mw * 16 + grp) * AW_STRIDE + kt * 8 + thr;
            unsigned ah0 = Ahi[abase],        ah1 = Ahi[abase + 8 * AW_STRIDE];
            unsigned ah2 = Ahi[abase + 4],    ah3 = Ahi[abase + 8 * AW_STRIDE + 4];
            unsigned al0 = Alo[abase],        al1 = Alo[abase + 8 * AW_STRIDE];
            unsigned al2 = Alo[abase + 4],    al3 = Alo[abase + 8 * AW_STRIDE + 4];

            const unsigned* bb = &Bw[cb * B_CHUNK_W + (nw * 3) * 256 + lane * 8];
#pragma unroll
            for (int g = 0; g < 3; g++) {
                uint4 bhi = *(const uint4*)&bb[g * 256];
                uint4 blo = *(const uint4*)&bb[g * 256 + 4];
                // j = 0
                mma_bf16(acc[0][g], ah0, ah1, ah2, ah3, bhi.x, bhi.y);
                mma_bf16(acc[0][g], ah0, ah1, ah2, ah3, blo.x, blo.y);
                mma_bf16(acc[0][g], al0, al1, al2, al3, bhi.x, bhi.y);
                // j = 1
                mma_bf16(acc[1][g], ah0, ah1, ah2, ah3, bhi.z, bhi.w);
                mma_bf16(acc[1][g], ah0, ah1, ah2, ah3, blo.z, blo.w);
                mma_bf16(acc[1][g], al0, al1, al2, al3, bhi.z, bhi.w);
            }
            if (havep) {
                uint4* db = (uint4*)&Bw[(cb ^ 1) * B_CHUNK_W];
                db[tid] = p1;
                if (tid < 128) db[256 + tid] = p2;
            }
            __syncthreads();
        }

        // ---- epilogue: gates + state update
#pragma unroll
        for (int j = 0; j < 2; j++) {
            const int hcol = hb + nw * 16 + j * 8 + thr * 2;
#pragma unroll
            for (int half = 0; half < 2; half++) {
                const int m = half ? m_b : m_a;
                const int sl = half ? seq_b : seq_a;
                const int ai = half * 2;
                const float2 hp = __ldcg((const float2*)&hin[((size_t)m << 9) + hcol]);
                float hn0, hn1;
                const size_t bt = (size_t)m * Tsz + t;
                if (t < sl) {
                    const float* gi = &GI[bt * (size_t)H3 + hcol];
                    const float2 gir = *(const float2*)&gi[0];
                    const float2 giz = *(const float2*)&gi[Hsz];
                    const float2 gin = *(const float2*)&gi[2 * Hsz];
                    const float ghr0 = acc[j][0][ai] + bh[j][0].x;
                    const float ghr1 = acc[j][0][ai + 1] + bh[j][0].y;
                    const float ghz0 = acc[j][1][ai] + bh[j][1].x;
                    const float ghz1 = acc[j][1][ai + 1] + bh[j][1].y;
                    const float ghn0 = acc[j][2][ai] + bh[j][2].x;
                    const float ghn1 = acc[j][2][ai + 1] + bh[j][2].y;
                    const float r0 = __fdividef(1.0f, 1.0f + __expf(-(gir.x + ghr0)));
                    const float r1 = __fdividef(1.0f, 1.0f + __expf(-(gir.y + ghr1)));
                    const float z0 = __fdividef(1.0f, 1.0f + __expf(-(giz.x + ghz0)));
                    const float z1 = __fdividef(1.0f, 1.0f + __expf(-(giz.y + ghz1)));
                    const float n0v = tanhf(gin.x + r0 * ghn0);
                    const float n1v = tanhf(gin.y + r1 * ghn1);
                    hn0 = (1.0f - z0) * n0v + z0 * hp.x;
                    hn1 = (1.0f - z1) * n1v + z1 * hp.y;
                    *(float2*)&ffin[bt * (size_t)Hsz + hcol] = make_float2(hn0, hn1);
                } else {
                    hn0 = hp.x; hn1 = hp.y;
                    *(float2*)&ffin[bt * (size_t)Hsz + hcol] = make_float2(0.0f, 0.0f);
                }
                *(float2*)&hout[((size_t)m << 9) + hcol] = make_float2(hn0, hn1);
                unsigned hpk = bf2pack(hn0, hn1);
                *(unsigned*)&hbh_out[((size_t)m << 9) + hcol] = hpk;
                __nv_bfloat162 h2 = *(__nv_bfloat162*)&hpk;
                float l0 = hn0 - __bfloat162float(__low2bfloat16(h2));
                float l1 = hn1 - __bfloat162float(__high2bfloat16(h2));
                *(unsigned*)&hbl_out[((size_t)m << 9) + hcol] = bf2pack(l0, l1);
            }
        }

        // ---- grid barrier
        if (t < Tsz - 1) {
            __syncthreads();
            if (tid == 0) {
                __threadfence();
                atomicAdd(&g_bar, 1u);
                const unsigned target = (unsigned)(t + 1) * (unsigned)gridDim.x;
                while (atomicAdd(&g_bar, 0u) < target) __nanosleep(64);
                __threadfence();
            }
            __syncthreads();
        }
    }
}

// ---------------- output GEMM: Y = hid @ W2 + b2, PAD-masked ---------------------
__global__ __launch_bounds__(256) void out_gemm_kernel(const float* __restrict__ W2,
                                                       const float* __restrict__ b2,
                                                       const int* __restrict__ seq,
                                                       float* __restrict__ Y) {
    const int m0 = blockIdx.x * 128;
    const int b  = m0 / Tsz;
    const int t0 = m0 % Tsz;
    const int tid = threadIdx.x;
    const int slen = seq[b];
    if (t0 >= slen) {
        float4 pv = make_float4(PADV, PADV, PADV, PADV);
#pragma unroll
        for (int l = 0; l < 8; l++) {
            int idx = tid + l * 256;
            *(float4*)&Y[(size_t)(m0 + (idx >> 4)) * OUTsz + (idx & 15) * 4] = pv;
        }
        return;
    }
    __shared__ float As[32][128];
    __shared__ float Bs[32][64];
    const int tx = tid % 16, ty = tid / 16;
    const int row0 = ty * 8, col0 = tx * 4;
    unsigned long long acc[8][2];
#pragma unroll
    for (int i = 0; i < 8; i++) { acc[i][0] = 0ULL; acc[i][1] = 0ULL; }

    for (int k0 = 0; k0 < FFsz; k0 += 32) {
#pragma unroll
        for (int l = 0; l < 4; l++) {
            int idx = tid + l * 256;
            int r = idx >> 3, c4 = (idx & 7) * 4;
            float4 v = *(const float4*)&g_hid[(size_t)(m0 + r) * FFsz + k0 + c4];
            As[c4 + 0][r] = v.x; As[c4 + 1][r] = v.y;
            As[c4 + 2][r] = v.z; As[c4 + 3][r] = v.w;
        }
#pragma unroll
        for (int l = 0; l < 2; l++) {
            int idx = tid + l * 256;
            int k = idx >> 4, c4 = (idx & 15) * 4;
            *(float4*)&Bs[k][c4] = *(const float4*)&W2[(size_t)(k0 + k) * OUTsz + c4];
        }
        __syncthreads();
#pragma unroll
        for (int k = 0; k < 32; k++) {
            float4 a0 = *(const float4*)&As[k][row0];
            float4 a1 = *(const float4*)&As[k][row0 + 4];
            unsigned long long b0 = *(const unsigned long long*)&Bs[k][col0];
            unsigned long long b1 = *(const unsigned long long*)&Bs[k][col0 + 2];
            float av[8] = {a0.x, a0.y, a0.z, a0.w, a1.x, a1.y, a1.z, a1.w};
#pragma unroll
            for (int i = 0; i < 8; i++) {
                unsigned long long ad = pack2(av[i], av[i]);
                fma2(acc[i][0], ad, b0);
                fma2(acc[i][1], ad, b1);
            }
        }
        __syncthreads();
    }
#pragma unroll
    for (int i = 0; i < 8; i++) {
        int m = m0 + row0 + i;
        int t = t0 + row0 + i;
        float o[4];
        unpack2(acc[i][0], o[0], o[1]);
        unpack2(acc[i][1], o[2], o[3]);
        float4 v;
        if (t < slen) {
            v = make_float4(o[0] + b2[col0 + 0], o[1] + b2[col0 + 1],
                            o[2] + b2[col0 + 2], o[3] + b2[col0 + 3]);
        } else {
            v = make_float4(PADV, PADV, PADV, PADV);
        }
        *(float4*)&Y[(size_t)m * OUTsz + col0] = v;
    }
}

// ---------------- launch ----------------
extern "C" void kernel_launch(void* const* d_in, const int* in_sizes, int n_in,
                              void* d_out, int out_size) {
    (void)in_sizes; (void)n_in; (void)out_size;
    const float* x    = (const float*)d_in[0];
    const int*   seq  = (const int*)d_in[1];
    const float* W_ih = (const float*)d_in[2];
    const float* W_hh = (const float*)d_in[3];
    const float* b_ih = (const float*)d_in[4];
    const float* b_hh = (const float*)d_in[5];
    const float* W1   = (const float*)d_in[6];
    const float* b1   = (const float*)d_in[7];
    const float* W2   = (const float*)d_in[8];
    const float* b2   = (const float*)d_in[9];
    float* Y = (float*)d_out;

    float *pGI = nullptr, *pFF = nullptr, *pHID = nullptr;
    cudaGetSymbolAddress((void**)&pGI, g_GI);
    cudaGetSymbolAddress((void**)&pFF, g_ffin);
    cudaGetSymbolAddress((void**)&pHID, g_hid);

    const int smem_bytes = (2 * A_WORDS + 2 * B_CHUNK_W) * 4;  // 145,408 B
    static bool attr_set = false;
    if (!attr_set) {
        cudaFuncSetAttribute(gru_mma, cudaFuncAttributeMaxDynamicSharedMemorySize,
                             smem_bytes);
        attr_set = true;
    }

    init_kernel<<<(Bsz * Hsz + 255) / 256, 256>>>();
    wprep_kernel<<<(16 * 32 * 2 * 3 * 32 + 255) / 256, 256>>>(W_hh);

    sgemm128<Fsz, H3, true, false, true>
        <<<dim3(BT / 128, H3 / 128), 256>>>(x, W_ih, b_ih, pGI, seq);

    gru_mma<<<128, 256, smem_bytes>>>(pGI, b_hh, seq, pFF);

    sgemm128<Hsz, FFsz, false, true, true>
        <<<dim3(BT / 128, FFsz / 128), 256>>>(pFF, W1, b1, pHID, seq);

    out_gemm_kernel<<<dim3(BT / 128), 256>>>(W2, b2, seq, Y);
}

// round 5
// speedup vs baseline: 2.1516x; 1.3454x over previous
#include <cuda_runtime.h>
#include <cuda_bf16.h>
#include <math.h>

#define Bsz   512
#define Tsz   256
#define Fsz   128
#define Hsz   512
#define FFsz  1024
#define OUTsz 64
#define H3    (3 * Hsz)
#define BT    (Bsz * Tsz)
#define PADV  (-999.0f)
#define BFRAG_WORDS 49152   // per-block_n W slice: 32kt*2nw*3g*32lane*8w

// ---------------- scratch ----------------
__device__ float g_GI[(size_t)BT * H3];
__device__ float g_ffin[(size_t)BT * Hsz];
__device__ float g_hid[(size_t)BT * FFsz];
// fragment-major h (bf16 hi/lo packed), ping-pong: [pp][m][kt][16 words]
__device__ unsigned g_hfrag[2][(size_t)Bsz * 32 * 16];
// W_hh fragments: [block_n][kt][nw][g][lane][8 words]
__device__ unsigned g_wfrag[16 * BFRAG_WORDS];
__device__ unsigned g_bar;

// ---------------- helpers ----------------
__device__ __forceinline__ unsigned long long pack2(float x, float y) {
    unsigned long long r;
    asm("mov.b64 %0,{%1,%2};" : "=l"(r) : "f"(x), "f"(y));
    return r;
}
__device__ __forceinline__ void fma2(unsigned long long& d, unsigned long long a,
                                     unsigned long long b) {
    asm("fma.rn.f32x2 %0,%1,%2,%0;" : "+l"(d) : "l"(a), "l"(b));
}
__device__ __forceinline__ void unpack2(unsigned long long v, float& x, float& y) {
    asm("mov.b64 {%0,%1},%2;" : "=f"(x), "=f"(y) : "l"(v));
}
__device__ __forceinline__ void mma_bf16(float* d, unsigned a0, unsigned a1,
                                         unsigned a2, unsigned a3,
                                         unsigned b0, unsigned b1) {
    asm volatile(
        "mma.sync.aligned.m16n8k16.row.col.f32.bf16.bf16.f32 "
        "{%0,%1,%2,%3},{%4,%5,%6,%7},{%8,%9},{%0,%1,%2,%3};"
        : "+f"(d[0]), "+f"(d[1]), "+f"(d[2]), "+f"(d[3])
        : "r"(a0), "r"(a1), "r"(a2), "r"(a3), "r"(b0), "r"(b1));
}
__device__ __forceinline__ unsigned bf2pack(float x, float y) {
    __nv_bfloat162 v = __floats2bfloat162_rn(x, y);
    return *(unsigned*)&v;
}
__device__ __forceinline__ void bfunpack(unsigned p, float& x, float& y) {
    __nv_bfloat162 v = *(__nv_bfloat162*)&p;
    x = __bfloat162float(__low2bfloat16(v));
    y = __bfloat162float(__high2bfloat16(v));
}

// ---------------- init ----------------
__global__ void init_kernel() {
    int i = blockIdx.x * blockDim.x + threadIdx.x;
    int tot = Bsz * 32 * 16;
    if (i < tot) g_hfrag[0][i] = 0u;
    if (i == 0) g_bar = 0u;
}

// ---------------- W_hh -> bf16 hi/lo fragment layout ----------------
__global__ void wprep_kernel(const float* __restrict__ W_hh) {
    int idx = blockIdx.x * blockDim.x + threadIdx.x;
    if (idx >= 16 * 32 * 2 * 3 * 32) return;
    int lane = idx & 31;
    int r = idx >> 5;
    int g = r % 3;  r /= 3;
    int nw = r & 1; r >>= 1;
    int kt = r & 31;
    int bn = r >> 5;
    int grp = lane >> 2, thr = lane & 3;

    unsigned w[8];
#pragma unroll
    for (int j = 0; j < 2; j++) {
        int n_row = g * Hsz + bn * 32 + nw * 16 + j * 8 + grp;
        const float* src = &W_hh[(size_t)n_row * Hsz + kt * 16 + thr * 2];
        float x0 = src[0], x1 = src[1], x8 = src[8], x9 = src[9];
        unsigned b0h = bf2pack(x0, x1);
        unsigned b1h = bf2pack(x8, x9);
        float h00, h01, h10, h11;
        bfunpack(b0h, h00, h01);
        bfunpack(b1h, h10, h11);
        w[0 + j * 2] = b0h;
        w[1 + j * 2] = b1h;
        w[4 + j * 2] = bf2pack(x0 - h00, x1 - h01);
        w[5 + j * 2] = bf2pack(x8 - h10, x9 - h11);
    }
    unsigned* dst = &g_wfrag[(size_t)((((bn * 32 + kt) * 2 + nw) * 3 + g) * 32 + lane) * 8];
#pragma unroll
    for (int i = 0; i < 8; i++) dst[i] = w[i];
}

// ---------------- generic 128x128 SGEMM (unchanged) ----------------
template <int KDIM, int NDIM, bool BTRANS, bool RELU, bool SKIP>
__global__ __launch_bounds__(256) void sgemm128(const float* __restrict__ A,
                                                const float* __restrict__ Bm,
                                                const float* __restrict__ bias,
                                                float* __restrict__ C,
                                                const int* __restrict__ seq) {
    const int m0 = blockIdx.x * 128;
    const int n0 = blockIdx.y * 128;
    if (SKIP) {
        int b = m0 / Tsz, t0 = m0 % Tsz;
        if (t0 >= seq[b]) return;
    }
    __shared__ float As[16][128];
    __shared__ float Bs[16][128];
    const int tid = threadIdx.x;
    const int tx = tid % 16, ty = tid / 16;
    const int row0 = ty * 8, col0 = tx * 8;
    unsigned long long acc[8][4];
#pragma unroll
    for (int i = 0; i < 8; i++)
#pragma unroll
        for (int j = 0; j < 4; j++) acc[i][j] = 0ULL;

    for (int k0 = 0; k0 < KDIM; k0 += 16) {
#pragma unroll
        for (int l = 0; l < 2; l++) {
            int idx = tid + l * 256;
            int r = idx >> 2, c4 = (idx & 3) * 4;
            float4 v = *(const float4*)&A[(size_t)(m0 + r) * KDIM + k0 + c4];
            As[c4 + 0][r] = v.x; As[c4 + 1][r] = v.y;
            As[c4 + 2][r] = v.z; As[c4 + 3][r] = v.w;
        }
        if (BTRANS) {
#pragma unroll
            for (int l = 0; l < 2; l++) {
                int idx = tid + l * 256;
                int n = idx >> 2, c4 = (idx & 3) * 4;
                float4 v = *(const float4*)&Bm[(size_t)(n0 + n) * KDIM + k0 + c4];
                Bs[c4 + 0][n] = v.x; Bs[c4 + 1][n] = v.y;
                Bs[c4 + 2][n] = v.z; Bs[c4 + 3][n] = v.w;
            }
        } else {
#pragma unroll
            for (int l = 0; l < 2; l++) {
                int idx = tid + l * 256;
                int k = idx >> 5, c4 = (idx & 31) * 4;
                *(float4*)&Bs[k][c4] =
                    *(const float4*)&Bm[(size_t)(k0 + k) * NDIM + n0 + c4];
            }
        }
        __syncthreads();
#pragma unroll
        for (int k = 0; k < 16; k++) {
            float4 a0 = *(const float4*)&As[k][row0];
            float4 a1 = *(const float4*)&As[k][row0 + 4];
            unsigned long long bb[4];
#pragma unroll
            for (int j = 0; j < 4; j++)
                bb[j] = *(const unsigned long long*)&Bs[k][col0 + j * 2];
            float av[8] = {a0.x, a0.y, a0.z, a0.w, a1.x, a1.y, a1.z, a1.w};
#pragma unroll
            for (int i = 0; i < 8; i++) {
                unsigned long long ad = pack2(av[i], av[i]);
#pragma unroll
                for (int j = 0; j < 4; j++) fma2(acc[i][j], ad, bb[j]);
            }
        }
        __syncthreads();
    }
#pragma unroll
    for (int i = 0; i < 8; i++) {
        float out[8];
#pragma unroll
        for (int j = 0; j < 4; j++) unpack2(acc[i][j], out[j * 2], out[j * 2 + 1]);
#pragma unroll
        for (int j = 0; j < 8; j++) {
            float v = out[j] + bias[n0 + col0 + j];
            if (RELU) v = fmaxf(v, 0.0f);
            out[j] = v;
        }
        float4* cp = (float4*)&C[(size_t)(m0 + row0 + i) * NDIM + n0 + col0];
        cp[0] = make_float4(out[0], out[1], out[2], out[3]);
        cp[1] = make_float4(out[4], out[5], out[6], out[7]);
    }
}

// ---------------- persistent tensor-core GRU, barrier-free mainloop -------------
// Grid=128. Block: 64 batch rows x 32 hidden (x3 gates). W frags persistent in
// smem (192KB). h in fragment-major gmem ping-pong (LDG.128 per row per kt).
// fp32 h carried in registers. One __syncthreads per step (grid barrier only).
__global__ __launch_bounds__(256, 1) void gru_mma(
    const float* __restrict__ GI, const float* __restrict__ b_hh,
    const int* __restrict__ seq, float* __restrict__ ffin) {
    extern __shared__ unsigned Bw[];   // [kt][nw][g][lane][8] = 192KB

    const int tid = threadIdx.x;
    const int lane = tid & 31;
    const int wid  = tid >> 5;
    const int mw = wid & 3, nw = wid >> 2;
    const int grp = lane >> 2, thr = lane & 3;
    const int m0 = (blockIdx.x >> 4) * 64;
    const int block_n = blockIdx.x & 15;
    const int hb = block_n * 32;
    const int kt_g = block_n * 2 + nw;     // kt group this thread's outputs land in

    // load W slice into persistent smem
    {
        const uint4* src = (const uint4*)&g_wfrag[(size_t)block_n * BFRAG_WORDS];
        uint4* dst = (uint4*)Bw;
        for (int i = tid; i < BFRAG_WORDS / 4; i += 256) dst[i] = src[i];
    }

    const int m_a = m0 + mw * 16 + grp;
    const int m_b = m_a + 8;
    const int seq_a = seq[m_a];
    const int seq_b = seq[m_b];

    float2 bh[2][3];
#pragma unroll
    for (int j = 0; j < 2; j++) {
        const int hcol = hb + nw * 16 + j * 8 + thr * 2;
#pragma unroll
        for (int g = 0; g < 3; g++) bh[j][g] = *(const float2*)&b_hh[g * Hsz + hcol];
    }

    float hreg[2][2][2];   // [half(m_a/m_b)][j][pair] fp32 hidden state
#pragma unroll
    for (int a = 0; a < 2; a++)
#pragma unroll
        for (int b = 0; b < 2; b++) { hreg[a][b][0] = 0.0f; hreg[a][b][1] = 0.0f; }

    __syncthreads();

    for (int t = 0; t < Tsz; ++t) {
        const int pp = t & 1;
        const unsigned* __restrict__ Af = g_hfrag[pp];
        unsigned* __restrict__ Ao = g_hfrag[pp ^ 1];

        // prefetch GI (valid or not; guarded at use)
        float2 pgi[2][2][3];   // [half][j][gate]
#pragma unroll
        for (int half = 0; half < 2; half++) {
            const int m = half ? m_b : m_a;
            const size_t gib = ((size_t)m * Tsz + t) * (size_t)H3;
#pragma unroll
            for (int j = 0; j < 2; j++) {
                const int hcol = hb + nw * 16 + j * 8 + thr * 2;
#pragma unroll
                for (int g = 0; g < 3; g++)
                    pgi[half][j][g] = *(const float2*)&GI[gib + g * Hsz + hcol];
            }
        }

        float accH[2][3][4], accL[2][3][4];
#pragma unroll
        for (int j = 0; j < 2; j++)
#pragma unroll
            for (int g = 0; g < 3; g++)
#pragma unroll
                for (int c = 0; c < 4; c++) { accH[j][g][c] = 0.0f; accL[j][g][c] = 0.0f; }

        // distance-2 prefetched A fragments (one LDG.128 per row per kt)
        uint4 pfA[2][2];
        const size_t abase_a = (size_t)m_a * 32;
        const size_t abase_b = (size_t)m_b * 32;
#pragma unroll
        for (int p = 0; p < 2; p++) {
            pfA[p][0] = __ldcg((const uint4*)&Af[(abase_a + p) * 16 + thr * 4]);
            pfA[p][1] = __ldcg((const uint4*)&Af[(abase_b + p) * 16 + thr * 4]);
        }

#pragma unroll 4
        for (int kt = 0; kt < 32; ++kt) {
            const uint4 ar0 = pfA[kt & 1][0];  // .x=ah0 .y=ah2 .z=al0 .w=al2
            const uint4 ar1 = pfA[kt & 1][1];  // .x=ah1 .y=ah3 .z=al1 .w=al3
            if (kt < 30) {
                pfA[kt & 1][0] = __ldcg((const uint4*)&Af[(abase_a + kt + 2) * 16 + thr * 4]);
                pfA[kt & 1][1] = __ldcg((const uint4*)&Af[(abase_b + kt + 2) * 16 + thr * 4]);
            }
            const unsigned* bb = &Bw[((kt * 2 + nw) * 3) * 256 + lane * 8];
#pragma unroll
            for (int g = 0; g < 3; g++) {
                uint4 bhi = *(const uint4*)&bb[g * 256];
                uint4 blo = *(const uint4*)&bb[g * 256 + 4];
                mma_bf16(accH[0][g], ar0.x, ar1.x, ar0.y, ar1.y, bhi.x, bhi.y);
                mma_bf16(accL[0][g], ar0.x, ar1.x, ar0.y, ar1.y, blo.x, blo.y);
                mma_bf16(accL[0][g], ar0.z, ar1.z, ar0.w, ar1.w, bhi.x, bhi.y);
                mma_bf16(accH[1][g], ar0.x, ar1.x, ar0.y, ar1.y, bhi.z, bhi.w);
                mma_bf16(accL[1][g], ar0.x, ar1.x, ar0.y, ar1.y, blo.z, blo.w);
                mma_bf16(accL[1][g], ar0.z, ar1.z, ar0.w, ar1.w, bhi.z, bhi.w);
            }
        }

        // epilogue: gates + state update (h stays in registers)
#pragma unroll
        for (int half = 0; half < 2; half++) {
            const int m = half ? m_b : m_a;
            const int sl = half ? seq_b : seq_a;
            const int ai = half * 2;
            const size_t bt = (size_t)m * Tsz + t;
#pragma unroll
            for (int j = 0; j < 2; j++) {
                const int hcol = hb + nw * 16 + j * 8 + thr * 2;
                const float hp0 = hreg[half][j][0];
                const float hp1 = hreg[half][j][1];
                if (t < sl) {
                    const float ghr0 = accH[j][0][ai] + accL[j][0][ai] + bh[j][0].x;
                    const float ghr1 = accH[j][0][ai + 1] + accL[j][0][ai + 1] + bh[j][0].y;
                    const float ghz0 = accH[j][1][ai] + accL[j][1][ai] + bh[j][1].x;
                    const float ghz1 = accH[j][1][ai + 1] + accL[j][1][ai + 1] + bh[j][1].y;
                    const float ghn0 = accH[j][2][ai] + accL[j][2][ai] + bh[j][2].x;
                    const float ghn1 = accH[j][2][ai + 1] + accL[j][2][ai + 1] + bh[j][2].y;
                    const float r0 = __fdividef(1.0f, 1.0f + __expf(-(pgi[half][j][0].x + ghr0)));
                    const float r1 = __fdividef(1.0f, 1.0f + __expf(-(pgi[half][j][0].y + ghr1)));
                    const float z0 = __fdividef(1.0f, 1.0f + __expf(-(pgi[half][j][1].x + ghz0)));
                    const float z1 = __fdividef(1.0f, 1.0f + __expf(-(pgi[half][j][1].y + ghz1)));
                    const float n0v = tanhf(pgi[half][j][2].x + r0 * ghn0);
                    const float n1v = tanhf(pgi[half][j][2].y + r1 * ghn1);
                    const float hn0 = (1.0f - z0) * n0v + z0 * hp0;
                    const float hn1 = (1.0f - z1) * n1v + z1 * hp1;
                    hreg[half][j][0] = hn0;
                    hreg[half][j][1] = hn1;
                    *(float2*)&ffin[bt * (size_t)Hsz + hcol] = make_float2(hn0, hn1);
                } else {
                    *(float2*)&ffin[bt * (size_t)Hsz + hcol] = make_float2(0.0f, 0.0f);
                }
            }
            // pack hi/lo fragment words and store (one STG.128 per row)
            unsigned w0h = bf2pack(hreg[half][0][0], hreg[half][0][1]);
            unsigned w1h = bf2pack(hreg[half][1][0], hreg[half][1][1]);
            float e00, e01, e10, e11;
            bfunpack(w0h, e00, e01);
            bfunpack(w1h, e10, e11);
            uint4 st;
            st.x = w0h;
            st.y = w1h;
            st.z = bf2pack(hreg[half][0][0] - e00, hreg[half][0][1] - e01);
            st.w = bf2pack(hreg[half][1][0] - e10, hreg[half][1][1] - e11);
            *(uint4*)&Ao[((size_t)m * 32 + kt_g) * 16 + thr * 4] = st;
        }

        // grid barrier
        if (t < Tsz - 1) {
            __threadfence();
            __syncthreads();
            if (tid == 0) {
                atomicAdd(&g_bar, 1u);
                const unsigned target = (unsigned)(t + 1) * (unsigned)gridDim.x;
                while (atomicAdd(&g_bar, 0u) < target) __nanosleep(64);
            }
            __syncthreads();
        }
    }
}

// ---------------- output GEMM: Y = hid @ W2 + b2, PAD-masked ---------------------
__global__ __launch_bounds__(256) void out_gemm_kernel(const float* __restrict__ W2,
                                                       const float* __restrict__ b2,
                                                       const int* __restrict__ seq,
                                                       float* __restrict__ Y) {
    const int m0 = blockIdx.x * 128;
    const int b  = m0 / Tsz;
    const int t0 = m0 % Tsz;
    const int tid = threadIdx.x;
    const int slen = seq[b];
    if (t0 >= slen) {
        float4 pv = make_float4(PADV, PADV, PADV, PADV);
#pragma unroll
        for (int l = 0; l < 8; l++) {
            int idx = tid + l * 256;
            *(float4*)&Y[(size_t)(m0 + (idx >> 4)) * OUTsz + (idx & 15) * 4] = pv;
        }
        return;
    }
    __shared__ float As[32][128];
    __shared__ float Bs[32][64];
    const int tx = tid % 16, ty = tid / 16;
    const int row0 = ty * 8, col0 = tx * 4;
    unsigned long long acc[8][2];
#pragma unroll
    for (int i = 0; i < 8; i++) { acc[i][0] = 0ULL; acc[i][1] = 0ULL; }

    for (int k0 = 0; k0 < FFsz; k0 += 32) {
#pragma unroll
        for (int l = 0; l < 4; l++) {
            int idx = tid + l * 256;
            int r = idx >> 3, c4 = (idx & 7) * 4;
            float4 v = *(const float4*)&g_hid[(size_t)(m0 + r) * FFsz + k0 + c4];
            As[c4 + 0][r] = v.x; As[c4 + 1][r] = v.y;
            As[c4 + 2][r] = v.z; As[c4 + 3][r] = v.w;
        }
#pragma unroll
        for (int l = 0; l < 2; l++) {
            int idx = tid + l * 256;
            int k = idx >> 4, c4 = (idx & 15) * 4;
            *(float4*)&Bs[k][c4] = *(const float4*)&W2[(size_t)(k0 + k) * OUTsz + c4];
        }
        __syncthreads();
#pragma unroll
        for (int k = 0; k < 32; k++) {
            float4 a0 = *(const float4*)&As[k][row0];
            float4 a1 = *(const float4*)&As[k][row0 + 4];
            unsigned long long b0 = *(const unsigned long long*)&Bs[k][col0];
            unsigned long long b1 = *(const unsigned long long*)&Bs[k][col0 + 2];
            float av[8] = {a0.x, a0.y, a0.z, a0.w, a1.x, a1.y, a1.z, a1.w};
#pragma unroll
            for (int i = 0; i < 8; i++) {
                unsigned long long ad = pack2(av[i], av[i]);
                fma2(acc[i][0], ad, b0);
                fma2(acc[i][1], ad, b1);
            }
        }
        __syncthreads();
    }
#pragma unroll
    for (int i = 0; i < 8; i++) {
        int m = m0 + row0 + i;
        int t = t0 + row0 + i;
        float o[4];
        unpack2(acc[i][0], o[0], o[1]);
        unpack2(acc[i][1], o[2], o[3]);
        float4 v;
        if (t < slen) {
            v = make_float4(o[0] + b2[col0 + 0], o[1] + b2[col0 + 1],
                            o[2] + b2[col0 + 2], o[3] + b2[col0 + 3]);
        } else {
            v = make_float4(PADV, PADV, PADV, PADV);
        }
        *(float4*)&Y[(size_t)m * OUTsz + col0] = v;
    }
}

// ---------------- launch ----------------
extern "C" void kernel_launch(void* const* d_in, const int* in_sizes, int n_in,
                              void* d_out, int out_size) {
    (void)in_sizes; (void)n_in; (void)out_size;
    const float* x    = (const float*)d_in[0];
    const int*   seq  = (const int*)d_in[1];
    const float* W_ih = (const float*)d_in[2];
    const float* W_hh = (const float*)d_in[3];
    const float* b_ih = (const float*)d_in[4];
    const float* b_hh = (const float*)d_in[5];
    const float* W1   = (const float*)d_in[6];
    const float* b1   = (const float*)d_in[7];
    const float* W2   = (const float*)d_in[8];
    const float* b2   = (const float*)d_in[9];
    float* Y = (float*)d_out;

    float *pGI = nullptr, *pFF = nullptr, *pHID = nullptr;
    cudaGetSymbolAddress((void**)&pGI, g_GI);
    cudaGetSymbolAddress((void**)&pFF, g_ffin);
    cudaGetSymbolAddress((void**)&pHID, g_hid);

    const int smem_bytes = BFRAG_WORDS * 4;   // 196,608 B persistent W frags
    static bool attr_set = false;
    if (!attr_set) {
        cudaFuncSetAttribute(gru_mma, cudaFuncAttributeMaxDynamicSharedMemorySize,
                             smem_bytes);
        attr_set = true;
    }

    init_kernel<<<(Bsz * 32 * 16 + 255) / 256, 256>>>();
    wprep_kernel<<<(16 * 32 * 2 * 3 * 32 + 255) / 256, 256>>>(W_hh);

    sgemm128<Fsz, H3, true, false, true>
        <<<dim3(BT / 128, H3 / 128), 256>>>(x, W_ih, b_ih, pGI, seq);

    gru_mma<<<128, 256, smem_bytes>>>(pGI, b_hh, seq, pFF);

    sgemm128<Hsz, FFsz, false, true, true>
        <<<dim3(BT / 128, FFsz / 128), 256>>>(pFF, W1, b1, pHID, seq);

    out_gemm_kernel<<<dim3(BT / 128), 256>>>(W2, b2, seq, Y);
}

// round 6
// speedup vs baseline: 2.3677x; 1.1005x over previous
#include <cuda_runtime.h>
#include <cuda_bf16.h>
#include <math.h>

#define Bsz   512
#define Tsz   256
#define Fsz   128
#define Hsz   512
#define FFsz  1024
#define OUTsz 64
#define H3    (3 * Hsz)
#define BT    (Bsz * Tsz)
#define PADV  (-999.0f)
#define BFRAG_WORDS 49152   // per-block_n W slice: 32kt*2nw*3g*2hl*32lane*4w

// ---------------- scratch ----------------
__device__ float g_GI[(size_t)BT * H3];
__device__ float g_ffin[(size_t)BT * Hsz];
__device__ float g_hid[(size_t)BT * FFsz];
// fragment-major h (bf16 hi/lo packed), ping-pong: [pp][m][kt][16 words]
__device__ unsigned g_hfrag[2][(size_t)Bsz * 32 * 16];
// W_hh fragments: [block_n][kt][nw][g][hi|lo][lane][4 words]
__device__ unsigned g_wfrag[16 * BFRAG_WORDS];
__device__ unsigned g_barg[8 * 32];   // per-m-group barrier counters (128B spaced)

// ---------------- helpers ----------------
__device__ __forceinline__ unsigned long long pack2(float x, float y) {
    unsigned long long r;
    asm("mov.b64 %0,{%1,%2};" : "=l"(r) : "f"(x), "f"(y));
    return r;
}
__device__ __forceinline__ void fma2(unsigned long long& d, unsigned long long a,
                                     unsigned long long b) {
    asm("fma.rn.f32x2 %0,%1,%2,%0;" : "+l"(d) : "l"(a), "l"(b));
}
__device__ __forceinline__ void unpack2(unsigned long long v, float& x, float& y) {
    asm("mov.b64 {%0,%1},%2;" : "=f"(x), "=f"(y) : "l"(v));
}
__device__ __forceinline__ void mma_bf16(float* d, unsigned a0, unsigned a1,
                                         unsigned a2, unsigned a3,
                                         unsigned b0, unsigned b1) {
    asm volatile(
        "mma.sync.aligned.m16n8k16.row.col.f32.bf16.bf16.f32 "
        "{%0,%1,%2,%3},{%4,%5,%6,%7},{%8,%9},{%0,%1,%2,%3};"
        : "+f"(d[0]), "+f"(d[1]), "+f"(d[2]), "+f"(d[3])
        : "r"(a0), "r"(a1), "r"(a2), "r"(a3), "r"(b0), "r"(b1));
}
__device__ __forceinline__ unsigned bf2pack(float x, float y) {
    __nv_bfloat162 v = __floats2bfloat162_rn(x, y);
    return *(unsigned*)&v;
}
__device__ __forceinline__ void bfunpack(unsigned p, float& x, float& y) {
    __nv_bfloat162 v = *(__nv_bfloat162*)&p;
    x = __bfloat162float(__low2bfloat16(v));
    y = __bfloat162float(__high2bfloat16(v));
}

// ---------------- init ----------------
__global__ void init_kernel() {
    int i = blockIdx.x * blockDim.x + threadIdx.x;
    int tot = Bsz * 32 * 16;
    if (i < tot) g_hfrag[0][i] = 0u;
    if (i < 8 * 32) g_barg[i] = 0u;
}

// ---------------- W_hh -> bf16 hi/lo fragment layout (conflict-free panels) -----
__global__ void wprep_kernel(const float* __restrict__ W_hh) {
    int idx = blockIdx.x * blockDim.x + threadIdx.x;
    if (idx >= 16 * 32 * 2 * 3 * 32) return;
    int lane = idx & 31;
    int r = idx >> 5;
    int g = r % 3;  r /= 3;
    int nw = r & 1; r >>= 1;
    int kt = r & 31;
    int bn = r >> 5;
    int grp = lane >> 2, thr = lane & 3;

    unsigned whi[4], wlo[4];
#pragma unroll
    for (int j = 0; j < 2; j++) {
        int n_row = g * Hsz + bn * 32 + nw * 16 + j * 8 + grp;
        const float* src = &W_hh[(size_t)n_row * Hsz + kt * 16 + thr * 2];
        float x0 = src[0], x1 = src[1], x8 = src[8], x9 = src[9];
        unsigned b0h = bf2pack(x0, x1);
        unsigned b1h = bf2pack(x8, x9);
        float h00, h01, h10, h11;
        bfunpack(b0h, h00, h01);
        bfunpack(b1h, h10, h11);
        whi[0 + j * 2] = b0h;
        whi[1 + j * 2] = b1h;
        wlo[0 + j * 2] = bf2pack(x0 - h00, x1 - h01);
        wlo[1 + j * 2] = bf2pack(x8 - h10, x9 - h11);
    }
    // layout: [bn][kt][nw][g][hl][lane][4]
    size_t base = ((size_t)bn * 32 + kt);
    base = ((base * 2 + nw) * 3 + g) * 2;
    unsigned* dhi = &g_wfrag[(base + 0) * 128 + lane * 4];
    unsigned* dlo = &g_wfrag[(base + 1) * 128 + lane * 4];
#pragma unroll
    for (int i = 0; i < 4; i++) { dhi[i] = whi[i]; dlo[i] = wlo[i]; }
}

// ---------------- generic 128x128 SGEMM (unchanged) ----------------
template <int KDIM, int NDIM, bool BTRANS, bool RELU, bool SKIP>
__global__ __launch_bounds__(256) void sgemm128(const float* __restrict__ A,
                                                const float* __restrict__ Bm,
                                                const float* __restrict__ bias,
                                                float* __restrict__ C,
                                                const int* __restrict__ seq) {
    const int m0 = blockIdx.x * 128;
    const int n0 = blockIdx.y * 128;
    if (SKIP) {
        int b = m0 / Tsz, t0 = m0 % Tsz;
        if (t0 >= seq[b]) return;
    }
    __shared__ float As[16][128];
    __shared__ float Bs[16][128];
    const int tid = threadIdx.x;
    const int tx = tid % 16, ty = tid / 16;
    const int row0 = ty * 8, col0 = tx * 8;
    unsigned long long acc[8][4];
#pragma unroll
    for (int i = 0; i < 8; i++)
#pragma unroll
        for (int j = 0; j < 4; j++) acc[i][j] = 0ULL;

    for (int k0 = 0; k0 < KDIM; k0 += 16) {
#pragma unroll
        for (int l = 0; l < 2; l++) {
            int idx = tid + l * 256;
            int r = idx >> 2, c4 = (idx & 3) * 4;
            float4 v = *(const float4*)&A[(size_t)(m0 + r) * KDIM + k0 + c4];
            As[c4 + 0][r] = v.x; As[c4 + 1][r] = v.y;
            As[c4 + 2][r] = v.z; As[c4 + 3][r] = v.w;
        }
        if (BTRANS) {
#pragma unroll
            for (int l = 0; l < 2; l++) {
                int idx = tid + l * 256;
                int n = idx >> 2, c4 = (idx & 3) * 4;
                float4 v = *(const float4*)&Bm[(size_t)(n0 + n) * KDIM + k0 + c4];
                Bs[c4 + 0][n] = v.x; Bs[c4 + 1][n] = v.y;
                Bs[c4 + 2][n] = v.z; Bs[c4 + 3][n] = v.w;
            }
        } else {
#pragma unroll
            for (int l = 0; l < 2; l++) {
                int idx = tid + l * 256;
                int k = idx >> 5, c4 = (idx & 31) * 4;
                *(float4*)&Bs[k][c4] =
                    *(const float4*)&Bm[(size_t)(k0 + k) * NDIM + n0 + c4];
            }
        }
        __syncthreads();
#pragma unroll
        for (int k = 0; k < 16; k++) {
            float4 a0 = *(const float4*)&As[k][row0];
            float4 a1 = *(const float4*)&As[k][row0 + 4];
            unsigned long long bb[4];
#pragma unroll
            for (int j = 0; j < 4; j++)
                bb[j] = *(const unsigned long long*)&Bs[k][col0 + j * 2];
            float av[8] = {a0.x, a0.y, a0.z, a0.w, a1.x, a1.y, a1.z, a1.w};
#pragma unroll
            for (int i = 0; i < 8; i++) {
                unsigned long long ad = pack2(av[i], av[i]);
#pragma unroll
                for (int j = 0; j < 4; j++) fma2(acc[i][j], ad, bb[j]);
            }
        }
        __syncthreads();
    }
#pragma unroll
    for (int i = 0; i < 8; i++) {
        float out[8];
#pragma unroll
        for (int j = 0; j < 4; j++) unpack2(acc[i][j], out[j * 2], out[j * 2 + 1]);
#pragma unroll
        for (int j = 0; j < 8; j++) {
            float v = out[j] + bias[n0 + col0 + j];
            if (RELU) v = fmaxf(v, 0.0f);
            out[j] = v;
        }
        float4* cp = (float4*)&C[(size_t)(m0 + row0 + i) * NDIM + n0 + col0];
        cp[0] = make_float4(out[0], out[1], out[2], out[3]);
        cp[1] = make_float4(out[4], out[5], out[6], out[7]);
    }
}

// ---------------- persistent tensor-core GRU -------------------------------------
// Grid=128. Block: 64 batch rows x 32 hidden (x3 gates). W frags persistent in
// smem (192KB, conflict-free panels). h in fragment-major gmem ping-pong.
// fp32 h in registers. Per-m-group (16-block) barrier between steps.
__global__ __launch_bounds__(256, 1) void gru_mma(
    const float* __restrict__ GI, const float* __restrict__ b_hh,
    const int* __restrict__ seq, float* __restrict__ ffin) {
    extern __shared__ unsigned Bw[];   // [kt][nw][g][hl][lane][4] = 192KB

    const int tid = threadIdx.x;
    const int lane = tid & 31;
    const int wid  = tid >> 5;
    const int mw = wid & 3, nw = wid >> 2;
    const int grp = lane >> 2, thr = lane & 3;
    const int mgrp = blockIdx.x >> 4;
    const int m0 = mgrp * 64;
    const int block_n = blockIdx.x & 15;
    const int hb = block_n * 32;
    const int kt_g = block_n * 2 + nw;

    // load W slice into persistent smem
    {
        const uint4* src = (const uint4*)&g_wfrag[(size_t)block_n * BFRAG_WORDS];
        uint4* dst = (uint4*)Bw;
        for (int i = tid; i < BFRAG_WORDS / 4; i += 256) dst[i] = src[i];
    }

    const int m_a = m0 + mw * 16 + grp;
    const int m_b = m_a + 8;
    const int seq_a = seq[m_a];
    const int seq_b = seq[m_b];

    float2 bh[2][3];
#pragma unroll
    for (int j = 0; j < 2; j++) {
        const int hcol = hb + nw * 16 + j * 8 + thr * 2;
#pragma unroll
        for (int g = 0; g < 3; g++) bh[j][g] = *(const float2*)&b_hh[g * Hsz + hcol];
    }

    float hreg[2][2][2];
#pragma unroll
    for (int a = 0; a < 2; a++)
#pragma unroll
        for (int b = 0; b < 2; b++) { hreg[a][b][0] = 0.0f; hreg[a][b][1] = 0.0f; }

    __syncthreads();

    for (int t = 0; t < Tsz; ++t) {
        const int pp = t & 1;
        const unsigned* __restrict__ Af = g_hfrag[pp];
        unsigned* __restrict__ Ao = g_hfrag[pp ^ 1];

        // prefetch GI
        float2 pgi[2][2][3];
#pragma unroll
        for (int half = 0; half < 2; half++) {
            const int m = half ? m_b : m_a;
            const size_t gib = ((size_t)m * Tsz + t) * (size_t)H3;
#pragma unroll
            for (int j = 0; j < 2; j++) {
                const int hcol = hb + nw * 16 + j * 8 + thr * 2;
#pragma unroll
                for (int g = 0; g < 3; g++)
                    pgi[half][j][g] = *(const float2*)&GI[gib + g * Hsz + hcol];
            }
        }

        float accH[2][3][4], accL[2][3][4];
#pragma unroll
        for (int j = 0; j < 2; j++)
#pragma unroll
            for (int g = 0; g < 3; g++)
#pragma unroll
                for (int c = 0; c < 4; c++) { accH[j][g][c] = 0.0f; accL[j][g][c] = 0.0f; }

        uint4 pfA[2][2];
        const size_t abase_a = (size_t)m_a * 32;
        const size_t abase_b = (size_t)m_b * 32;
#pragma unroll
        for (int p = 0; p < 2; p++) {
            pfA[p][0] = __ldcg((const uint4*)&Af[(abase_a + p) * 16 + thr * 4]);
            pfA[p][1] = __ldcg((const uint4*)&Af[(abase_b + p) * 16 + thr * 4]);
        }

#pragma unroll 4
        for (int kt = 0; kt < 32; ++kt) {
            const uint4 ar0 = pfA[kt & 1][0];  // .x=ah0 .y=ah2 .z=al0 .w=al2
            const uint4 ar1 = pfA[kt & 1][1];  // .x=ah1 .y=ah3 .z=al1 .w=al3
            if (kt < 30) {
                pfA[kt & 1][0] = __ldcg((const uint4*)&Af[(abase_a + kt + 2) * 16 + thr * 4]);
                pfA[kt & 1][1] = __ldcg((const uint4*)&Af[(abase_b + kt + 2) * 16 + thr * 4]);
            }
            const unsigned* bb = &Bw[((kt * 2 + nw) * 3) * 256 + lane * 4];
#pragma unroll
            for (int g = 0; g < 3; g++) {
                uint4 bhi = *(const uint4*)&bb[g * 256];         // hi panel
                uint4 blo = *(const uint4*)&bb[g * 256 + 128];   // lo panel
                mma_bf16(accH[0][g], ar0.x, ar1.x, ar0.y, ar1.y, bhi.x, bhi.y);
                mma_bf16(accL[0][g], ar0.x, ar1.x, ar0.y, ar1.y, blo.x, blo.y);
                mma_bf16(accL[0][g], ar0.z, ar1.z, ar0.w, ar1.w, bhi.x, bhi.y);
                mma_bf16(accH[1][g], ar0.x, ar1.x, ar0.y, ar1.y, bhi.z, bhi.w);
                mma_bf16(accL[1][g], ar0.x, ar1.x, ar0.y, ar1.y, blo.z, blo.w);
                mma_bf16(accL[1][g], ar0.z, ar1.z, ar0.w, ar1.w, bhi.z, bhi.w);
            }
        }

        // epilogue: gates + state update
#pragma unroll
        for (int half = 0; half < 2; half++) {
            const int m = half ? m_b : m_a;
            const int sl = half ? seq_b : seq_a;
            const int ai = half * 2;
            const size_t bt = (size_t)m * Tsz + t;
#pragma unroll
            for (int j = 0; j < 2; j++) {
                const int hcol = hb + nw * 16 + j * 8 + thr * 2;
                const float hp0 = hreg[half][j][0];
                const float hp1 = hreg[half][j][1];
                if (t < sl) {
                    const float ghr0 = accH[j][0][ai] + accL[j][0][ai] + bh[j][0].x;
                    const float ghr1 = accH[j][0][ai + 1] + accL[j][0][ai + 1] + bh[j][0].y;
                    const float ghz0 = accH[j][1][ai] + accL[j][1][ai] + bh[j][1].x;
                    const float ghz1 = accH[j][1][ai + 1] + accL[j][1][ai + 1] + bh[j][1].y;
                    const float ghn0 = accH[j][2][ai] + accL[j][2][ai] + bh[j][2].x;
                    const float ghn1 = accH[j][2][ai + 1] + accL[j][2][ai + 1] + bh[j][2].y;
                    const float r0 = __fdividef(1.0f, 1.0f + __expf(-(pgi[half][j][0].x + ghr0)));
                    const float r1 = __fdividef(1.0f, 1.0f + __expf(-(pgi[half][j][0].y + ghr1)));
                    const float z0 = __fdividef(1.0f, 1.0f + __expf(-(pgi[half][j][1].x + ghz0)));
                    const float z1 = __fdividef(1.0f, 1.0f + __expf(-(pgi[half][j][1].y + ghz1)));
                    const float n0v = tanhf(pgi[half][j][2].x + r0 * ghn0);
                    const float n1v = tanhf(pgi[half][j][2].y + r1 * ghn1);
                    const float hn0 = (1.0f - z0) * n0v + z0 * hp0;
                    const float hn1 = (1.0f - z1) * n1v + z1 * hp1;
                    hreg[half][j][0] = hn0;
                    hreg[half][j][1] = hn1;
                    *(float2*)&ffin[bt * (size_t)Hsz + hcol] = make_float2(hn0, hn1);
                } else {
                    *(float2*)&ffin[bt * (size_t)Hsz + hcol] = make_float2(0.0f, 0.0f);
                }
            }
            unsigned w0h = bf2pack(hreg[half][0][0], hreg[half][0][1]);
            unsigned w1h = bf2pack(hreg[half][1][0], hreg[half][1][1]);
            float e00, e01, e10, e11;
            bfunpack(w0h, e00, e01);
            bfunpack(w1h, e10, e11);
            uint4 st;
            st.x = w0h;
            st.y = w1h;
            st.z = bf2pack(hreg[half][0][0] - e00, hreg[half][0][1] - e01);
            st.w = bf2pack(hreg[half][1][0] - e10, hreg[half][1][1] - e11);
            *(uint4*)&Ao[((size_t)m * 32 + kt_g) * 16 + thr * 4] = st;
        }

        // per-m-group barrier (16 blocks)
        if (t < Tsz - 1) {
            __threadfence();
            __syncthreads();
            if (tid == 0) {
                unsigned* ctr = &g_barg[mgrp * 32];
                atomicAdd(ctr, 1u);
                const unsigned target = 16u * (unsigned)(t + 1);
                while (atomicAdd(ctr, 0u) < target) __nanosleep(32);
            }
            __syncthreads();
        }
    }
}

// ---------------- output GEMM: Y = hid @ W2 + b2, PAD-masked ---------------------
__global__ __launch_bounds__(256) void out_gemm_kernel(const float* __restrict__ W2,
                                                       const float* __restrict__ b2,
                                                       const int* __restrict__ seq,
                                                       float* __restrict__ Y) {
    const int m0 = blockIdx.x * 128;
    const int b  = m0 / Tsz;
    const int t0 = m0 % Tsz;
    const int tid = threadIdx.x;
    const int slen = seq[b];
    if (t0 >= slen) {
        float4 pv = make_float4(PADV, PADV, PADV, PADV);
#pragma unroll
        for (int l = 0; l < 8; l++) {
            int idx = tid + l * 256;
            *(float4*)&Y[(size_t)(m0 + (idx >> 4)) * OUTsz + (idx & 15) * 4] = pv;
        }
        return;
    }
    __shared__ float As[32][128];
    __shared__ float Bs[32][64];
    const int tx = tid % 16, ty = tid / 16;
    const int row0 = ty * 8, col0 = tx * 4;
    unsigned long long acc[8][2];
#pragma unroll
    for (int i = 0; i < 8; i++) { acc[i][0] = 0ULL; acc[i][1] = 0ULL; }

    for (int k0 = 0; k0 < FFsz; k0 += 32) {
#pragma unroll
        for (int l = 0; l < 4; l++) {
            int idx = tid + l * 256;
            int r = idx >> 3, c4 = (idx & 7) * 4;
            float4 v = *(const float4*)&g_hid[(size_t)(m0 + r) * FFsz + k0 + c4];
            As[c4 + 0][r] = v.x; As[c4 + 1][r] = v.y;
            As[c4 + 2][r] = v.z; As[c4 + 3][r] = v.w;
        }
#pragma unroll
        for (int l = 0; l < 2; l++) {
            int idx = tid + l * 256;
            int k = idx >> 4, c4 = (idx & 15) * 4;
            *(float4*)&Bs[k][c4] = *(const float4*)&W2[(size_t)(k0 + k) * OUTsz + c4];
        }
        __syncthreads();
#pragma unroll
        for (int k = 0; k < 32; k++) {
            float4 a0 = *(const float4*)&As[k][row0];
            float4 a1 = *(const float4*)&As[k][row0 + 4];
            unsigned long long b0 = *(const unsigned long long*)&Bs[k][col0];
            unsigned long long b1 = *(const unsigned long long*)&Bs[k][col0 + 2];
            float av[8] = {a0.x, a0.y, a0.z, a0.w, a1.x, a1.y, a1.z, a1.w};
#pragma unroll
            for (int i = 0; i < 8; i++) {
                unsigned long long ad = pack2(av[i], av[i]);
                fma2(acc[i][0], ad, b0);
                fma2(acc[i][1], ad, b1);
            }
        }
        __syncthreads();
    }
#pragma unroll
    for (int i = 0; i < 8; i++) {
        int m = m0 + row0 + i;
        int t = t0 + row0 + i;
        float o[4];
        unpack2(acc[i][0], o[0], o[1]);
        unpack2(acc[i][1], o[2], o[3]);
        float4 v;
        if (t < slen) {
            v = make_float4(o[0] + b2[col0 + 0], o[1] + b2[col0 + 1],
                            o[2] + b2[col0 + 2], o[3] + b2[col0 + 3]);
        } else {
            v = make_float4(PADV, PADV, PADV, PADV);
        }
        *(float4*)&Y[(size_t)m * OUTsz + col0] = v;
    }
}

// ---------------- launch ----------------
extern "C" void kernel_launch(void* const* d_in, const int* in_sizes, int n_in,
                              void* d_out, int out_size) {
    (void)in_sizes; (void)n_in; (void)out_size;
    const float* x    = (const float*)d_in[0];
    const int*   seq  = (const int*)d_in[1];
    const float* W_ih = (const float*)d_in[2];
    const float* W_hh = (const float*)d_in[3];
    const float* b_ih = (const float*)d_in[4];
    const float* b_hh = (const float*)d_in[5];
    const float* W1   = (const float*)d_in[6];
    const float* b1   = (const float*)d_in[7];
    const float* W2   = (const float*)d_in[8];
    const float* b2   = (const float*)d_in[9];
    float* Y = (float*)d_out;

    float *pGI = nullptr, *pFF = nullptr, *pHID = nullptr;
    cudaGetSymbolAddress((void**)&pGI, g_GI);
    cudaGetSymbolAddress((void**)&pFF, g_ffin);
    cudaGetSymbolAddress((void**)&pHID, g_hid);

    const int smem_bytes = BFRAG_WORDS * 4;
    static bool attr_set = false;
    if (!attr_set) {
        cudaFuncSetAttribute(gru_mma, cudaFuncAttributeMaxDynamicSharedMemorySize,
                             smem_bytes);
        attr_set = true;
    }

    init_kernel<<<(Bsz * 32 * 16 + 255) / 256, 256>>>();
    wprep_kernel<<<(16 * 32 * 2 * 3 * 32 + 255) / 256, 256>>>(W_hh);

    sgemm128<Fsz, H3, true, false, true>
        <<<dim3(BT / 128, H3 / 128), 256>>>(x, W_ih, b_ih, pGI, seq);

    gru_mma<<<128, 256, smem_bytes>>>(pGI, b_hh, seq, pFF);

    sgemm128<Hsz, FFsz, false, true, true>
        <<<dim3(BT / 128, FFsz / 128), 256>>>(pFF, W1, b1, pHID, seq);

    out_gemm_kernel<<<dim3(BT / 128), 256>>>(W2, b2, seq, Y);
}